// round 1
// baseline (speedup 1.0000x reference)
#include <cuda_runtime.h>
#include <math.h>

#define BATCH 2
#define CH    512
#define DQK   64
#define NPIX  4096   // 64*64

// ---- scratch (allocation-free: __device__ globals) ----
__device__ float g_q[(size_t)BATCH * DQK * NPIX];           // [b, d, n]   2 MB
__device__ float g_k[(size_t)BATCH * DQK * NPIX];           // [b, d, n]   2 MB
__device__ float g_v[(size_t)BATCH * CH  * NPIX];           // [b, c, n]  16 MB
__device__ float g_p[(size_t)BATCH * NPIX * NPIX];          // [b, i, j] 128 MB (scores -> probs in place)

// ============================================================
// Stage 1: projection  out[b,m,n] = sum_c W[m,c] * x[b,c,n] + bias[m]
// tiles: BM=64 (m), BN=64 (n), BK=16 ; 256 threads, 4x4 micro-tile
// ============================================================
__global__ __launch_bounds__(256) void proj_kernel(
    const float* __restrict__ W, const float* __restrict__ bias,
    const float* __restrict__ x, float* __restrict__ out, int M)
{
    const int b  = blockIdx.z;
    const int m0 = blockIdx.y * 64;
    const int n0 = blockIdx.x * 64;
    const float* X = x + (size_t)b * CH * NPIX;

    __shared__ float Ws[16][65];   // [k][m]
    __shared__ float Xs[16][64];   // [k][n]

    const int tid = threadIdx.x;
    const int tm = (tid >> 4) << 2;      // 0..60
    const int tn = (tid & 15) << 2;      // 0..60

    float acc[4][4] = {};

    for (int k0 = 0; k0 < CH; k0 += 16) {
        // W tile [64m x 16k] -> Ws[k][m]
        #pragma unroll
        for (int t = tid; t < 64 * 16; t += 256) {
            int m  = t >> 4;
            int kk = t & 15;
            Ws[kk][m] = W[(size_t)(m0 + m) * CH + k0 + kk];
        }
        // X tile [16k x 64n]
        #pragma unroll
        for (int t = tid; t < 16 * 64; t += 256) {
            int kk = t >> 6;
            int n  = t & 63;
            Xs[kk][n] = X[(size_t)(k0 + kk) * NPIX + n0 + n];
        }
        __syncthreads();
        #pragma unroll
        for (int kk = 0; kk < 16; kk++) {
            float a[4], bb[4];
            #pragma unroll
            for (int u = 0; u < 4; u++) a[u]  = Ws[kk][tm + u];
            #pragma unroll
            for (int u = 0; u < 4; u++) bb[u] = Xs[kk][tn + u];
            #pragma unroll
            for (int u = 0; u < 4; u++)
                #pragma unroll
                for (int v = 0; v < 4; v++)
                    acc[u][v] = fmaf(a[u], bb[v], acc[u][v]);
        }
        __syncthreads();
    }

    float* O = out + (size_t)b * M * NPIX;
    #pragma unroll
    for (int u = 0; u < 4; u++) {
        float bv = bias[m0 + tm + u];
        #pragma unroll
        for (int v = 0; v < 4; v++)
            O[(size_t)(m0 + tm + u) * NPIX + n0 + tn + v] = acc[u][v] + bv;
    }
}

// ============================================================
// Stage 2: scores  S[b,i,j] = sum_d q[b,d,i] * k[b,d,j]
// full K=64 resident in smem; BM=BN=64; 256 threads, 4x4 micro-tile
// ============================================================
__global__ __launch_bounds__(256) void scores_kernel()
{
    const int b  = blockIdx.z;
    const int i0 = blockIdx.y * 64;
    const int j0 = blockIdx.x * 64;
    const float* Q = g_q + (size_t)b * DQK * NPIX;
    const float* K = g_k + (size_t)b * DQK * NPIX;

    __shared__ float Qs[64][65];   // [d][i]
    __shared__ float Ks[64][65];   // [d][j]

    const int tid = threadIdx.x;
    const int ti = (tid >> 4) << 2;
    const int tj = (tid & 15) << 2;

    #pragma unroll
    for (int t = tid; t < 64 * 64; t += 256) {
        int d = t >> 6;
        int i = t & 63;
        Qs[d][i] = Q[(size_t)d * NPIX + i0 + i];
        Ks[d][i] = K[(size_t)d * NPIX + j0 + i];
    }
    __syncthreads();

    float acc[4][4] = {};
    #pragma unroll
    for (int d = 0; d < 64; d++) {
        float a[4], bb[4];
        #pragma unroll
        for (int u = 0; u < 4; u++) a[u]  = Qs[d][ti + u];
        #pragma unroll
        for (int u = 0; u < 4; u++) bb[u] = Ks[d][tj + u];
        #pragma unroll
        for (int u = 0; u < 4; u++)
            #pragma unroll
            for (int v = 0; v < 4; v++)
                acc[u][v] = fmaf(a[u], bb[v], acc[u][v]);
    }

    float* S = g_p + (size_t)b * NPIX * NPIX;
    #pragma unroll
    for (int u = 0; u < 4; u++)
        #pragma unroll
        for (int v = 0; v < 4; v++)
            S[(size_t)(i0 + ti + u) * NPIX + j0 + tj + v] = acc[u][v];
}

// ============================================================
// Stage 3: softmax over j for each (b,i) row. One block per row.
// Whole row (4096 f) lives in registers: 256 thr * 4 float4.
// ============================================================
__global__ __launch_bounds__(256) void softmax_kernel()
{
    const size_t row = blockIdx.x;                 // 0 .. B*NPIX-1
    float* S = g_p + row * NPIX;
    const int tid = threadIdx.x;

    float4 vals[4];
    float m = -1e30f;
    #pragma unroll
    for (int t = 0; t < 4; t++) {
        vals[t] = reinterpret_cast<float4*>(S)[tid + t * 256];
        m = fmaxf(m, fmaxf(fmaxf(vals[t].x, vals[t].y), fmaxf(vals[t].z, vals[t].w)));
    }

    __shared__ float red[8];
    // warp-reduce max
    #pragma unroll
    for (int o = 16; o; o >>= 1) m = fmaxf(m, __shfl_xor_sync(0xffffffffu, m, o));
    if ((tid & 31) == 0) red[tid >> 5] = m;
    __syncthreads();
    m = red[0];
    #pragma unroll
    for (int w = 1; w < 8; w++) m = fmaxf(m, red[w]);
    __syncthreads();

    float l = 0.f;
    #pragma unroll
    for (int t = 0; t < 4; t++) {
        vals[t].x = __expf(vals[t].x - m);
        vals[t].y = __expf(vals[t].y - m);
        vals[t].z = __expf(vals[t].z - m);
        vals[t].w = __expf(vals[t].w - m);
        l += (vals[t].x + vals[t].y) + (vals[t].z + vals[t].w);
    }
    #pragma unroll
    for (int o = 16; o; o >>= 1) l += __shfl_xor_sync(0xffffffffu, l, o);
    if ((tid & 31) == 0) red[tid >> 5] = l;
    __syncthreads();
    l = 0.f;
    #pragma unroll
    for (int w = 0; w < 8; w++) l += red[w];

    const float inv = 1.0f / l;
    #pragma unroll
    for (int t = 0; t < 4; t++) {
        vals[t].x *= inv; vals[t].y *= inv; vals[t].z *= inv; vals[t].w *= inv;
        reinterpret_cast<float4*>(S)[tid + t * 256] = vals[t];
    }
}

// ============================================================
// Stage 4: res[b,c,i] = sum_j V[b,c,j] * P[b,i,j] ;  out = gamma*res + x
// BM=64 (c), BN=64 (i), BK=32 ; 256 threads, 4x4 micro-tile
// ============================================================
__global__ __launch_bounds__(256) void pv_kernel(
    const float* __restrict__ x, const float* __restrict__ gamma_p,
    float* __restrict__ out)
{
    const int b  = blockIdx.z;
    const int c0 = blockIdx.y * 64;
    const int i0 = blockIdx.x * 64;
    const float* V = g_v + (size_t)b * CH * NPIX;
    const float* P = g_p + (size_t)b * NPIX * NPIX;

    __shared__ float Vs[32][65];   // [k][c]
    __shared__ float Ps[32][65];   // [k][i]

    const int tid = threadIdx.x;
    const int tc = (tid >> 4) << 2;
    const int ti = (tid & 15) << 2;

    float acc[4][4] = {};

    for (int k0 = 0; k0 < NPIX; k0 += 32) {
        #pragma unroll
        for (int t = tid; t < 64 * 32; t += 256) {
            int c  = t >> 5;
            int kk = t & 31;
            Vs[kk][c] = V[(size_t)(c0 + c) * NPIX + k0 + kk];
        }
        #pragma unroll
        for (int t = tid; t < 64 * 32; t += 256) {
            int i  = t >> 5;
            int kk = t & 31;
            Ps[kk][i] = P[(size_t)(i0 + i) * NPIX + k0 + kk];
        }
        __syncthreads();
        #pragma unroll
        for (int kk = 0; kk < 32; kk++) {
            float a[4], bb[4];
            #pragma unroll
            for (int u = 0; u < 4; u++) a[u]  = Vs[kk][tc + u];
            #pragma unroll
            for (int u = 0; u < 4; u++) bb[u] = Ps[kk][ti + u];
            #pragma unroll
            for (int u = 0; u < 4; u++)
                #pragma unroll
                for (int v = 0; v < 4; v++)
                    acc[u][v] = fmaf(a[u], bb[v], acc[u][v]);
        }
        __syncthreads();
    }

    const float g = *gamma_p;
    const float* Xb = x   + (size_t)b * CH * NPIX;
    float*       Ob = out + (size_t)b * CH * NPIX;
    #pragma unroll
    for (int u = 0; u < 4; u++)
        #pragma unroll
        for (int v = 0; v < 4; v++) {
            size_t idx = (size_t)(c0 + tc + u) * NPIX + i0 + ti + v;
            Ob[idx] = fmaf(g, acc[u][v], Xb[idx]);
        }
}

// ============================================================
// launch
// ============================================================
extern "C" void kernel_launch(void* const* d_in, const int* in_sizes, int n_in,
                              void* d_out, int out_size)
{
    const float* x     = (const float*)d_in[0];
    const float* Wq    = (const float*)d_in[1];
    const float* bq    = (const float*)d_in[2];
    const float* Wk    = (const float*)d_in[3];
    const float* bk    = (const float*)d_in[4];
    const float* Wv    = (const float*)d_in[5];
    const float* bv    = (const float*)d_in[6];
    const float* gamma = (const float*)d_in[7];
    float* out = (float*)d_out;

    float* q; cudaGetSymbolAddress((void**)&q, g_q);
    float* k; cudaGetSymbolAddress((void**)&k, g_k);
    float* v; cudaGetSymbolAddress((void**)&v, g_v);

    // Stage 1: projections
    {
        dim3 grid(NPIX / 64, DQK / 64, BATCH);
        proj_kernel<<<grid, 256>>>(Wq, bq, x, q, DQK);
        proj_kernel<<<grid, 256>>>(Wk, bk, x, k, DQK);
        dim3 gridv(NPIX / 64, CH / 64, BATCH);
        proj_kernel<<<gridv, 256>>>(Wv, bv, x, v, CH);
    }
    // Stage 2: scores
    {
        dim3 grid(NPIX / 64, NPIX / 64, BATCH);
        scores_kernel<<<grid, 256>>>();
    }
    // Stage 3: softmax
    softmax_kernel<<<BATCH * NPIX, 256>>>();
    // Stage 4: PV + epilogue
    {
        dim3 grid(NPIX / 64, CH / 64, BATCH);
        pv_kernel<<<grid, 256>>>(x, gamma, out);
    }
}

// round 4
// speedup vs baseline: 2.3955x; 2.3955x over previous
#include <cuda_runtime.h>
#include <math.h>
#include <stdint.h>

#define BATCH 2
#define CH    512
#define DQK   64
#define NPIX  4096   // 64*64

// ---- scratch (allocation-free: __device__ globals) ----
__device__ float g_q[(size_t)BATCH * DQK * NPIX];           // [b, d, n]   2 MB
__device__ float g_k[(size_t)BATCH * DQK * NPIX];           // [b, d, n]   2 MB
__device__ float g_v[(size_t)BATCH * CH  * NPIX];           // [b, c, n]  16 MB
__device__ float g_p[(size_t)BATCH * NPIX * NPIX];          // [b, i, j] 128 MB (scores -> probs in place)

// ============================================================
// Stage 1: projection  out[b,m,n] = sum_c W[m,c] * x[b,c,n] + bias[m]
// ============================================================
__global__ __launch_bounds__(256) void proj_kernel(
    const float* __restrict__ W, const float* __restrict__ bias,
    const float* __restrict__ x, float* __restrict__ out, int M)
{
    const int b  = blockIdx.z;
    const int m0 = blockIdx.y * 64;
    const int n0 = blockIdx.x * 64;
    const float* X = x + (size_t)b * CH * NPIX;

    __shared__ float Ws[16][65];   // [k][m]
    __shared__ float Xs[16][64];   // [k][n]

    const int tid = threadIdx.x;
    const int tm = (tid >> 4) << 2;
    const int tn = (tid & 15) << 2;

    float acc[4][4] = {};

    for (int k0 = 0; k0 < CH; k0 += 16) {
        #pragma unroll
        for (int t = tid; t < 64 * 16; t += 256) {
            int m  = t >> 4;
            int kk = t & 15;
            Ws[kk][m] = W[(size_t)(m0 + m) * CH + k0 + kk];
        }
        #pragma unroll
        for (int t = tid; t < 16 * 64; t += 256) {
            int kk = t >> 6;
            int n  = t & 63;
            Xs[kk][n] = X[(size_t)(k0 + kk) * NPIX + n0 + n];
        }
        __syncthreads();
        #pragma unroll
        for (int kk = 0; kk < 16; kk++) {
            float a[4], bb[4];
            #pragma unroll
            for (int u = 0; u < 4; u++) a[u]  = Ws[kk][tm + u];
            #pragma unroll
            for (int u = 0; u < 4; u++) bb[u] = Xs[kk][tn + u];
            #pragma unroll
            for (int u = 0; u < 4; u++)
                #pragma unroll
                for (int v = 0; v < 4; v++)
                    acc[u][v] = fmaf(a[u], bb[v], acc[u][v]);
        }
        __syncthreads();
    }

    float* O = out + (size_t)b * M * NPIX;
    #pragma unroll
    for (int u = 0; u < 4; u++) {
        float bv = bias[m0 + tm + u];
        #pragma unroll
        for (int v = 0; v < 4; v++)
            O[(size_t)(m0 + tm + u) * NPIX + n0 + tn + v] = acc[u][v] + bv;
    }
}

// ============================================================
// Stage 2: scores (fp32 SIMT -- precision-critical, pre-softmax)
// ============================================================
__global__ __launch_bounds__(256) void scores_kernel()
{
    const int b  = blockIdx.z;
    const int i0 = blockIdx.y * 64;
    const int j0 = blockIdx.x * 64;
    const float* Q = g_q + (size_t)b * DQK * NPIX;
    const float* K = g_k + (size_t)b * DQK * NPIX;

    __shared__ float Qs[64][65];
    __shared__ float Ks[64][65];

    const int tid = threadIdx.x;
    const int ti = (tid >> 4) << 2;
    const int tj = (tid & 15) << 2;

    #pragma unroll
    for (int t = tid; t < 64 * 64; t += 256) {
        int d = t >> 6;
        int i = t & 63;
        Qs[d][i] = Q[(size_t)d * NPIX + i0 + i];
        Ks[d][i] = K[(size_t)d * NPIX + j0 + i];
    }
    __syncthreads();

    float acc[4][4] = {};
    #pragma unroll
    for (int d = 0; d < 64; d++) {
        float a[4], bb[4];
        #pragma unroll
        for (int u = 0; u < 4; u++) a[u]  = Qs[d][ti + u];
        #pragma unroll
        for (int u = 0; u < 4; u++) bb[u] = Ks[d][tj + u];
        #pragma unroll
        for (int u = 0; u < 4; u++)
            #pragma unroll
            for (int v = 0; v < 4; v++)
                acc[u][v] = fmaf(a[u], bb[v], acc[u][v]);
    }

    float* S = g_p + (size_t)b * NPIX * NPIX;
    #pragma unroll
    for (int u = 0; u < 4; u++)
        #pragma unroll
        for (int v = 0; v < 4; v++)
            S[(size_t)(i0 + ti + u) * NPIX + j0 + tj + v] = acc[u][v];
}

// ============================================================
// Stage 3: softmax (row-resident in registers)
// ============================================================
__global__ __launch_bounds__(256) void softmax_kernel()
{
    const size_t row = blockIdx.x;
    float* S = g_p + row * NPIX;
    const int tid = threadIdx.x;

    float4 vals[4];
    float m = -1e30f;
    #pragma unroll
    for (int t = 0; t < 4; t++) {
        vals[t] = reinterpret_cast<float4*>(S)[tid + t * 256];
        m = fmaxf(m, fmaxf(fmaxf(vals[t].x, vals[t].y), fmaxf(vals[t].z, vals[t].w)));
    }

    __shared__ float red[8];
    #pragma unroll
    for (int o = 16; o; o >>= 1) m = fmaxf(m, __shfl_xor_sync(0xffffffffu, m, o));
    if ((tid & 31) == 0) red[tid >> 5] = m;
    __syncthreads();
    m = red[0];
    #pragma unroll
    for (int w = 1; w < 8; w++) m = fmaxf(m, red[w]);
    __syncthreads();

    float l = 0.f;
    #pragma unroll
    for (int t = 0; t < 4; t++) {
        vals[t].x = __expf(vals[t].x - m);
        vals[t].y = __expf(vals[t].y - m);
        vals[t].z = __expf(vals[t].z - m);
        vals[t].w = __expf(vals[t].w - m);
        l += (vals[t].x + vals[t].y) + (vals[t].z + vals[t].w);
    }
    #pragma unroll
    for (int o = 16; o; o >>= 1) l += __shfl_xor_sync(0xffffffffu, l, o);
    if ((tid & 31) == 0) red[tid >> 5] = l;
    __syncthreads();
    l = 0.f;
    #pragma unroll
    for (int w = 0; w < 8; w++) l += red[w];

    const float inv = 1.0f / l;
    #pragma unroll
    for (int t = 0; t < 4; t++) {
        vals[t].x *= inv; vals[t].y *= inv; vals[t].z *= inv; vals[t].w *= inv;
        reinterpret_cast<float4*>(S)[tid + t * 256] = vals[t];
    }
}

// ============================================================
// Stage 4: tf32 tensor-core PV GEMM
// res[b,c,i] = sum_j V[b,c,j] * P[b,i,j] ; out = gamma*res + x
// Block tile: 128(c) x 128(i), K-tile 32. 8 warps (2x4), warp tile 64x32.
// mma.sync.m16n8k8.tf32 ; ldmatrix from XOR-swizzled smem.
// ============================================================
#define PV_BM 128
#define PV_BN 128
#define PV_BK 32

__device__ __forceinline__ uint32_t f2tf32(float f) {
    uint32_t r;
    asm("cvt.rna.tf32.f32 %0, %1;" : "=r"(r) : "f"(f));
    return r;
}

__device__ __forceinline__ void ldm_x4(uint32_t& r0, uint32_t& r1, uint32_t& r2, uint32_t& r3,
                                       uint32_t addr) {
    asm volatile("ldmatrix.sync.aligned.m8n8.x4.shared.b16 {%0,%1,%2,%3}, [%4];"
                 : "=r"(r0), "=r"(r1), "=r"(r2), "=r"(r3) : "r"(addr));
}

__device__ __forceinline__ void mma_tf32(float& c0, float& c1, float& c2, float& c3,
                                         uint32_t a0, uint32_t a1, uint32_t a2, uint32_t a3,
                                         uint32_t b0, uint32_t b1) {
    asm volatile(
        "mma.sync.aligned.m16n8k8.row.col.f32.tf32.tf32.f32 "
        "{%0,%1,%2,%3}, {%4,%5,%6,%7}, {%8,%9}, {%0,%1,%2,%3};"
        : "+f"(c0), "+f"(c1), "+f"(c2), "+f"(c3)
        : "r"(a0), "r"(a1), "r"(a2), "r"(a3), "r"(b0), "r"(b1));
}

__global__ __launch_bounds__(256, 2) void pv_mma_kernel(
    const float* __restrict__ x, const float* __restrict__ gamma_p,
    float* __restrict__ out)
{
    const int b  = blockIdx.z;
    const int c0 = blockIdx.y * PV_BM;
    const int i0 = blockIdx.x * PV_BN;
    const float* V = g_v + (size_t)b * CH * NPIX;
    const float* P = g_p + (size_t)b * NPIX * NPIX;

    // swizzled tiles: physical float4 index = row*8 + (c4 ^ (row&7))
    __shared__ uint32_t As[PV_BM * PV_BK];   // V tile  [c][j]
    __shared__ uint32_t Bs[PV_BN * PV_BK];   // P tile  [i][j]

    const int tid  = threadIdx.x;
    const int wid  = tid >> 5;
    const int lane = tid & 31;
    const int warp_m = wid >> 2;       // 0..1
    const int warp_n = wid & 3;        // 0..3

    float acc[4][4][4] = {};           // [mt][nt][frag]

    const uint32_t As_base = (uint32_t)__cvta_generic_to_shared(As);
    const uint32_t Bs_base = (uint32_t)__cvta_generic_to_shared(Bs);

    // ldmatrix lane-address components (constant across K-tiles)
    const int lt = lane >> 3;          // tile index 0..3
    const int lr = lane & 7;           // row within tile
    // A: tile -> (m_half = lt&1, k_quad_half = lt>>1)
    const int a_row_local = warp_m * 64 + (lt & 1) * 8 + lr;  // + mt*16
    // B: tile -> (n_tile_half = lt>>1, k_quad_half = lt&1)
    const int b_row_local = warp_n * 32 + (lt >> 1) * 8 + lr; // + nt_pair*16

    for (int k0 = 0; k0 < NPIX; k0 += PV_BK) {
        // --- load tiles (fp32 -> tf32 on the way in) ---
        #pragma unroll
        for (int it = 0; it < 4; it++) {
            int t4  = it * 256 + tid;         // float4 index in 128x8 grid
            int row = t4 >> 3;
            int c4  = t4 & 7;
            float4 va = reinterpret_cast<const float4*>(V + (size_t)(c0 + row) * NPIX + k0)[c4];
            float4 vb = reinterpret_cast<const float4*>(P + (size_t)(i0 + row) * NPIX + k0)[c4];
            int idx = (row << 3) + (c4 ^ (row & 7));
            As[idx * 4 + 0] = f2tf32(va.x);
            As[idx * 4 + 1] = f2tf32(va.y);
            As[idx * 4 + 2] = f2tf32(va.z);
            As[idx * 4 + 3] = f2tf32(va.w);
            Bs[idx * 4 + 0] = f2tf32(vb.x);
            Bs[idx * 4 + 1] = f2tf32(vb.y);
            Bs[idx * 4 + 2] = f2tf32(vb.z);
            Bs[idx * 4 + 3] = f2tf32(vb.w);
        }
        __syncthreads();

        // --- compute ---
        #pragma unroll
        for (int ks = 0; ks < PV_BK / 8; ks++) {
            // B fragments: 4 n-tiles via 2 ldmatrix.x4
            uint32_t bfr[4][2];
            #pragma unroll
            for (int np = 0; np < 2; np++) {
                int row = b_row_local + np * 16;
                int c4  = ks * 2 + (lt & 1);
                uint32_t addr = Bs_base + (uint32_t)(((row << 3) + (c4 ^ (row & 7))) << 4);
                ldm_x4(bfr[np * 2][0], bfr[np * 2][1], bfr[np * 2 + 1][0], bfr[np * 2 + 1][1], addr);
            }
            #pragma unroll
            for (int mt = 0; mt < 4; mt++) {
                int row = a_row_local + mt * 16;
                int c4  = ks * 2 + (lt >> 1);
                uint32_t addr = As_base + (uint32_t)(((row << 3) + (c4 ^ (row & 7))) << 4);
                uint32_t a0, a1, a2, a3;
                ldm_x4(a0, a1, a2, a3, addr);
                #pragma unroll
                for (int nt = 0; nt < 4; nt++)
                    mma_tf32(acc[mt][nt][0], acc[mt][nt][1], acc[mt][nt][2], acc[mt][nt][3],
                             a0, a1, a2, a3, bfr[nt][0], bfr[nt][1]);
            }
        }
        __syncthreads();
    }

    // --- epilogue: out = gamma*acc + x ---
    const float g = *gamma_p;
    const float* Xb = x   + (size_t)b * CH * NPIX;
    float*       Ob = out + (size_t)b * CH * NPIX;
    const int gq = lane >> 2;          // 0..7
    const int qc = (lane & 3) * 2;     // 0,2,4,6

    #pragma unroll
    for (int mt = 0; mt < 4; mt++) {
        int c_base = c0 + warp_m * 64 + mt * 16;
        #pragma unroll
        for (int nt = 0; nt < 4; nt++) {
            int i_base = i0 + warp_n * 32 + nt * 8;
            #pragma unroll
            for (int h = 0; h < 2; h++) {   // h=0 -> rows 0-7 (c0,c1); h=1 -> rows 8-15 (c2,c3)
                size_t idx = (size_t)(c_base + gq + h * 8) * NPIX + i_base + qc;
                float2 xv = *reinterpret_cast<const float2*>(Xb + idx);
                float2 ov;
                ov.x = fmaf(g, acc[mt][nt][h * 2 + 0], xv.x);
                ov.y = fmaf(g, acc[mt][nt][h * 2 + 1], xv.y);
                *reinterpret_cast<float2*>(Ob + idx) = ov;
            }
        }
    }
}

// ============================================================
// launch
// ============================================================
extern "C" void kernel_launch(void* const* d_in, const int* in_sizes, int n_in,
                              void* d_out, int out_size)
{
    const float* x     = (const float*)d_in[0];
    const float* Wq    = (const float*)d_in[1];
    const float* bq    = (const float*)d_in[2];
    const float* Wk    = (const float*)d_in[3];
    const float* bk    = (const float*)d_in[4];
    const float* Wv    = (const float*)d_in[5];
    const float* bv    = (const float*)d_in[6];
    const float* gamma = (const float*)d_in[7];
    float* out = (float*)d_out;

    float* q; cudaGetSymbolAddress((void**)&q, g_q);
    float* k; cudaGetSymbolAddress((void**)&k, g_k);
    float* v; cudaGetSymbolAddress((void**)&v, g_v);

    {
        dim3 grid(NPIX / 64, DQK / 64, BATCH);
        proj_kernel<<<grid, 256>>>(Wq, bq, x, q, DQK);
        proj_kernel<<<grid, 256>>>(Wk, bk, x, k, DQK);
        dim3 gridv(NPIX / 64, CH / 64, BATCH);
        proj_kernel<<<gridv, 256>>>(Wv, bv, x, v, CH);
    }
    {
        dim3 grid(NPIX / 64, NPIX / 64, BATCH);
        scores_kernel<<<grid, 256>>>();
    }
    softmax_kernel<<<BATCH * NPIX, 256>>>();
    {
        dim3 grid(NPIX / PV_BN, CH / PV_BM, BATCH);
        pv_mma_kernel<<<grid, 256>>>(x, gamma, out);
    }
}

// round 5
// speedup vs baseline: 3.4065x; 1.4220x over previous
#include <cuda_runtime.h>
#include <math.h>
#include <stdint.h>

#define BATCH 2
#define CH    512
#define DQK   64
#define NPIX  4096   // 64*64

// ---- scratch (allocation-free: __device__ globals) ----
__device__ __align__(16) float g_qt[(size_t)BATCH * NPIX * DQK];   // [b, n, d]   2 MB
__device__ __align__(16) float g_kt[(size_t)BATCH * NPIX * DQK];   // [b, n, d]   2 MB
__device__ __align__(16) float g_v [(size_t)BATCH * CH  * NPIX];   // [b, c, n]  16 MB
__device__ __align__(16) float g_xt[(size_t)BATCH * NPIX * CH];    // [b, n, c]  16 MB
__device__ __align__(16) float g_p [(size_t)BATCH * NPIX * NPIX];  // [b, i, j] 128 MB

// ============================================================
// tf32 mma helpers (validated in R4)
// ============================================================
__device__ __forceinline__ uint32_t f2tf32(float f) {
    uint32_t r;
    asm("cvt.rna.tf32.f32 %0, %1;" : "=r"(r) : "f"(f));
    return r;
}

__device__ __forceinline__ void ldm_x4(uint32_t& r0, uint32_t& r1, uint32_t& r2, uint32_t& r3,
                                       uint32_t addr) {
    asm volatile("ldmatrix.sync.aligned.m8n8.x4.shared.b16 {%0,%1,%2,%3}, [%4];"
                 : "=r"(r0), "=r"(r1), "=r"(r2), "=r"(r3) : "r"(addr));
}

__device__ __forceinline__ void mma_tf32(float& c0, float& c1, float& c2, float& c3,
                                         uint32_t a0, uint32_t a1, uint32_t a2, uint32_t a3,
                                         uint32_t b0, uint32_t b1) {
    asm volatile(
        "mma.sync.aligned.m16n8k8.row.col.f32.tf32.tf32.f32 "
        "{%0,%1,%2,%3}, {%4,%5,%6,%7}, {%8,%9}, {%0,%1,%2,%3};"
        : "+f"(c0), "+f"(c1), "+f"(c2), "+f"(c3)
        : "r"(a0), "r"(a1), "r"(a2), "r"(a3), "r"(b0), "r"(b1));
}

// ============================================================
// Generic NT tf32 mainloop: C[128,128] += A[128,K] * B[128,K]^T
// A, B point at tile origins; lda/ldb in elements (mult of 4).
// 256 threads, 8 warps (2x4), warp tile 64x32, K-tile 32.
// ============================================================
template<int K_TOTAL>
__device__ __forceinline__ void nt_mma_mainloop(
    const float* __restrict__ A, int lda,
    const float* __restrict__ B, int ldb,
    uint32_t* As, uint32_t* Bs, float (&acc)[4][4][4])
{
    const int tid  = threadIdx.x;
    const int lane = tid & 31;
    const int warp_m = (tid >> 5) >> 2;
    const int warp_n = (tid >> 5) & 3;

    const uint32_t As_base = (uint32_t)__cvta_generic_to_shared(As);
    const uint32_t Bs_base = (uint32_t)__cvta_generic_to_shared(Bs);

    const int lt = lane >> 3;
    const int lr = lane & 7;
    const int a_row_local = warp_m * 64 + (lt & 1) * 8 + lr;
    const int b_row_local = warp_n * 32 + (lt >> 1) * 8 + lr;

    for (int k0 = 0; k0 < K_TOTAL; k0 += 32) {
        #pragma unroll
        for (int it = 0; it < 4; it++) {
            int t4  = it * 256 + tid;
            int row = t4 >> 3;
            int c4  = t4 & 7;
            float4 va = reinterpret_cast<const float4*>(A + (size_t)row * lda + k0)[c4];
            float4 vb = reinterpret_cast<const float4*>(B + (size_t)row * ldb + k0)[c4];
            int idx = (row << 3) + (c4 ^ (row & 7));
            As[idx * 4 + 0] = f2tf32(va.x);
            As[idx * 4 + 1] = f2tf32(va.y);
            As[idx * 4 + 2] = f2tf32(va.z);
            As[idx * 4 + 3] = f2tf32(va.w);
            Bs[idx * 4 + 0] = f2tf32(vb.x);
            Bs[idx * 4 + 1] = f2tf32(vb.y);
            Bs[idx * 4 + 2] = f2tf32(vb.z);
            Bs[idx * 4 + 3] = f2tf32(vb.w);
        }
        __syncthreads();

        #pragma unroll
        for (int ks = 0; ks < 4; ks++) {
            uint32_t bfr[4][2];
            #pragma unroll
            for (int np = 0; np < 2; np++) {
                int row = b_row_local + np * 16;
                int c4  = ks * 2 + (lt & 1);
                uint32_t addr = Bs_base + (uint32_t)(((row << 3) + (c4 ^ (row & 7))) << 4);
                ldm_x4(bfr[np * 2][0], bfr[np * 2][1], bfr[np * 2 + 1][0], bfr[np * 2 + 1][1], addr);
            }
            #pragma unroll
            for (int mt = 0; mt < 4; mt++) {
                int row = a_row_local + mt * 16;
                int c4  = ks * 2 + (lt >> 1);
                uint32_t addr = As_base + (uint32_t)(((row << 3) + (c4 ^ (row & 7))) << 4);
                uint32_t a0, a1, a2, a3;
                ldm_x4(a0, a1, a2, a3, addr);
                #pragma unroll
                for (int nt = 0; nt < 4; nt++)
                    mma_tf32(acc[mt][nt][0], acc[mt][nt][1], acc[mt][nt][2], acc[mt][nt][3],
                             a0, a1, a2, a3, bfr[nt][0], bfr[nt][1]);
            }
        }
        __syncthreads();
    }
}

// ============================================================
// Stage 0: transpose x[b,c,n] -> xt[b,n,c]
// ============================================================
__global__ __launch_bounds__(256) void transpose_kernel(const float* __restrict__ x)
{
    __shared__ float tile[32][33];
    const int b  = blockIdx.z;
    const int n0 = blockIdx.x * 32;
    const int c0 = blockIdx.y * 32;
    const int tx = threadIdx.x & 31;
    const int ty = threadIdx.x >> 5;   // 0..7

    const float* X = x + (size_t)b * CH * NPIX;
    float* XT = g_xt + (size_t)b * NPIX * CH;

    #pragma unroll
    for (int r = 0; r < 4; r++) {
        int c = ty + r * 8;
        tile[c][tx] = X[(size_t)(c0 + c) * NPIX + n0 + tx];
    }
    __syncthreads();
    #pragma unroll
    for (int r = 0; r < 4; r++) {
        int n = ty + r * 8;
        XT[(size_t)(n0 + n) * CH + c0 + tx] = tile[tx][n];
    }
}

// ============================================================
// Stage 1a: q/k projection (fp32 SIMT, precision-critical),
// writes TRANSPOSED output qt[b,n,d] via smem staging.
// M=64 (full d), N-tile 64, K=512.
// ============================================================
__global__ __launch_bounds__(256) void proj_qk_kernel(
    const float* __restrict__ W, const float* __restrict__ bias,
    const float* __restrict__ x, float* __restrict__ outT)
{
    const int b  = blockIdx.z;
    const int n0 = blockIdx.x * 64;
    const float* X = x + (size_t)b * CH * NPIX;

    __shared__ float Ws[16][65];
    __shared__ float Xs[16][64];
    __shared__ float Os[64][65];

    const int tid = threadIdx.x;
    const int tm = (tid >> 4) << 2;
    const int tn = (tid & 15) << 2;

    float acc[4][4] = {};

    for (int k0 = 0; k0 < CH; k0 += 16) {
        #pragma unroll
        for (int t = tid; t < 64 * 16; t += 256) {
            int m  = t >> 4;
            int kk = t & 15;
            Ws[kk][m] = W[(size_t)m * CH + k0 + kk];
        }
        #pragma unroll
        for (int t = tid; t < 16 * 64; t += 256) {
            int kk = t >> 6;
            int n  = t & 63;
            Xs[kk][n] = X[(size_t)(k0 + kk) * NPIX + n0 + n];
        }
        __syncthreads();
        #pragma unroll
        for (int kk = 0; kk < 16; kk++) {
            float a[4], bb[4];
            #pragma unroll
            for (int u = 0; u < 4; u++) a[u]  = Ws[kk][tm + u];
            #pragma unroll
            for (int u = 0; u < 4; u++) bb[u] = Xs[kk][tn + u];
            #pragma unroll
            for (int u = 0; u < 4; u++)
                #pragma unroll
                for (int v = 0; v < 4; v++)
                    acc[u][v] = fmaf(a[u], bb[v], acc[u][v]);
        }
        __syncthreads();
    }

    // stage (with bias) into smem, then write transposed [n][d] coalesced
    #pragma unroll
    for (int u = 0; u < 4; u++) {
        float bv = bias[tm + u];
        #pragma unroll
        for (int v = 0; v < 4; v++)
            Os[tm + u][tn + v] = acc[u][v] + bv;
    }
    __syncthreads();

    float* OT = outT + (size_t)b * NPIX * DQK;
    const int n_local = tid >> 2;          // 0..63
    const int m_base  = (tid & 3) * 16;    // 0,16,32,48
    #pragma unroll
    for (int j = 0; j < 4; j++) {
        int m = m_base + j * 4;
        float4 vv;
        vv.x = Os[m + 0][n_local];
        vv.y = Os[m + 1][n_local];
        vv.z = Os[m + 2][n_local];
        vv.w = Os[m + 3][n_local];
        *reinterpret_cast<float4*>(OT + (size_t)(n0 + n_local) * DQK + m) = vv;
    }
}

// ============================================================
// Stage 1b: V projection, tf32 mma.
// v[b,m,n] = sum_c Wv[m,c] * xt[b,n,c] + bv[m]
// ============================================================
__global__ __launch_bounds__(256, 2) void projv_mma_kernel(
    const float* __restrict__ Wv, const float* __restrict__ bv)
{
    const int b  = blockIdx.z;
    const int m0 = blockIdx.y * 128;
    const int n0 = blockIdx.x * 128;

    __shared__ uint32_t As[128 * 32];
    __shared__ uint32_t Bs[128 * 32];

    const float* A = Wv + (size_t)m0 * CH;
    const float* B = g_xt + ((size_t)b * NPIX + n0) * CH;

    float acc[4][4][4] = {};
    nt_mma_mainloop<CH>(A, CH, B, CH, As, Bs, acc);

    const int tid  = threadIdx.x;
    const int lane = tid & 31;
    const int warp_m = (tid >> 5) >> 2;
    const int warp_n = (tid >> 5) & 3;
    const int gq = lane >> 2;
    const int qc = (lane & 3) * 2;

    float* Vb = g_v + (size_t)b * CH * NPIX;
    #pragma unroll
    for (int mt = 0; mt < 4; mt++) {
        int m_base = m0 + warp_m * 64 + mt * 16;
        #pragma unroll
        for (int nt = 0; nt < 4; nt++) {
            int n_base = n0 + warp_n * 32 + nt * 8;
            #pragma unroll
            for (int h = 0; h < 2; h++) {
                int m = m_base + gq + h * 8;
                float bias = bv[m];
                float2 ov;
                ov.x = acc[mt][nt][h * 2 + 0] + bias;
                ov.y = acc[mt][nt][h * 2 + 1] + bias;
                *reinterpret_cast<float2*>(Vb + (size_t)m * NPIX + n_base + qc) = ov;
            }
        }
    }
}

// ============================================================
// Stage 2: scores, tf32 mma.  S[b,i,j] = qt[b,i,:] . kt[b,j,:]
// ============================================================
__global__ __launch_bounds__(256, 2) void scores_mma_kernel()
{
    const int b  = blockIdx.z;
    const int i0 = blockIdx.y * 128;
    const int j0 = blockIdx.x * 128;

    __shared__ uint32_t As[128 * 32];
    __shared__ uint32_t Bs[128 * 32];

    const float* A = g_qt + ((size_t)b * NPIX + i0) * DQK;
    const float* B = g_kt + ((size_t)b * NPIX + j0) * DQK;

    float acc[4][4][4] = {};
    nt_mma_mainloop<DQK>(A, DQK, B, DQK, As, Bs, acc);

    const int tid  = threadIdx.x;
    const int lane = tid & 31;
    const int warp_m = (tid >> 5) >> 2;
    const int warp_n = (tid >> 5) & 3;
    const int gq = lane >> 2;
    const int qc = (lane & 3) * 2;

    float* S = g_p + (size_t)b * NPIX * NPIX;
    #pragma unroll
    for (int mt = 0; mt < 4; mt++) {
        int i_base = i0 + warp_m * 64 + mt * 16;
        #pragma unroll
        for (int nt = 0; nt < 4; nt++) {
            int j_base = j0 + warp_n * 32 + nt * 8;
            #pragma unroll
            for (int h = 0; h < 2; h++) {
                float2 ov;
                ov.x = acc[mt][nt][h * 2 + 0];
                ov.y = acc[mt][nt][h * 2 + 1];
                *reinterpret_cast<float2*>(S + (size_t)(i_base + gq + h * 8) * NPIX + j_base + qc) = ov;
            }
        }
    }
}

// ============================================================
// Stage 3: softmax (row-resident in registers)
// ============================================================
__global__ __launch_bounds__(256) void softmax_kernel()
{
    const size_t row = blockIdx.x;
    float* S = g_p + row * NPIX;
    const int tid = threadIdx.x;

    float4 vals[4];
    float m = -1e30f;
    #pragma unroll
    for (int t = 0; t < 4; t++) {
        vals[t] = reinterpret_cast<float4*>(S)[tid + t * 256];
        m = fmaxf(m, fmaxf(fmaxf(vals[t].x, vals[t].y), fmaxf(vals[t].z, vals[t].w)));
    }

    __shared__ float red[8];
    #pragma unroll
    for (int o = 16; o; o >>= 1) m = fmaxf(m, __shfl_xor_sync(0xffffffffu, m, o));
    if ((tid & 31) == 0) red[tid >> 5] = m;
    __syncthreads();
    m = red[0];
    #pragma unroll
    for (int w = 1; w < 8; w++) m = fmaxf(m, red[w]);
    __syncthreads();

    float l = 0.f;
    #pragma unroll
    for (int t = 0; t < 4; t++) {
        vals[t].x = __expf(vals[t].x - m);
        vals[t].y = __expf(vals[t].y - m);
        vals[t].z = __expf(vals[t].z - m);
        vals[t].w = __expf(vals[t].w - m);
        l += (vals[t].x + vals[t].y) + (vals[t].z + vals[t].w);
    }
    #pragma unroll
    for (int o = 16; o; o >>= 1) l += __shfl_xor_sync(0xffffffffu, l, o);
    if ((tid & 31) == 0) red[tid >> 5] = l;
    __syncthreads();
    l = 0.f;
    #pragma unroll
    for (int w = 0; w < 8; w++) l += red[w];

    const float inv = 1.0f / l;
    #pragma unroll
    for (int t = 0; t < 4; t++) {
        vals[t].x *= inv; vals[t].y *= inv; vals[t].z *= inv; vals[t].w *= inv;
        reinterpret_cast<float4*>(S)[tid + t * 256] = vals[t];
    }
}

// ============================================================
// Stage 4: PV, tf32 mma.  out = gamma * (V P^T) + x
// ============================================================
__global__ __launch_bounds__(256, 2) void pv_mma_kernel(
    const float* __restrict__ x, const float* __restrict__ gamma_p,
    float* __restrict__ out)
{
    const int b  = blockIdx.z;
    const int c0 = blockIdx.y * 128;
    const int i0 = blockIdx.x * 128;

    __shared__ uint32_t As[128 * 32];
    __shared__ uint32_t Bs[128 * 32];

    const float* A = g_v + (size_t)b * CH * NPIX + (size_t)c0 * NPIX;
    const float* B = g_p + (size_t)b * NPIX * NPIX + (size_t)i0 * NPIX;

    float acc[4][4][4] = {};
    nt_mma_mainloop<NPIX>(A, NPIX, B, NPIX, As, Bs, acc);

    const int tid  = threadIdx.x;
    const int lane = tid & 31;
    const int warp_m = (tid >> 5) >> 2;
    const int warp_n = (tid >> 5) & 3;
    const int gq = lane >> 2;
    const int qc = (lane & 3) * 2;

    const float g = *gamma_p;
    const float* Xb = x   + (size_t)b * CH * NPIX;
    float*       Ob = out + (size_t)b * CH * NPIX;

    #pragma unroll
    for (int mt = 0; mt < 4; mt++) {
        int c_base = c0 + warp_m * 64 + mt * 16;
        #pragma unroll
        for (int nt = 0; nt < 4; nt++) {
            int i_base = i0 + warp_n * 32 + nt * 8;
            #pragma unroll
            for (int h = 0; h < 2; h++) {
                size_t idx = (size_t)(c_base + gq + h * 8) * NPIX + i_base + qc;
                float2 xv = *reinterpret_cast<const float2*>(Xb + idx);
                float2 ov;
                ov.x = fmaf(g, acc[mt][nt][h * 2 + 0], xv.x);
                ov.y = fmaf(g, acc[mt][nt][h * 2 + 1], xv.y);
                *reinterpret_cast<float2*>(Ob + idx) = ov;
            }
        }
    }
}

// ============================================================
// launch
// ============================================================
extern "C" void kernel_launch(void* const* d_in, const int* in_sizes, int n_in,
                              void* d_out, int out_size)
{
    const float* x     = (const float*)d_in[0];
    const float* Wq    = (const float*)d_in[1];
    const float* bq    = (const float*)d_in[2];
    const float* Wk    = (const float*)d_in[3];
    const float* bk    = (const float*)d_in[4];
    const float* Wv    = (const float*)d_in[5];
    const float* bv    = (const float*)d_in[6];
    const float* gamma = (const float*)d_in[7];
    float* out = (float*)d_out;

    float* qt; cudaGetSymbolAddress((void**)&qt, g_qt);
    float* kt; cudaGetSymbolAddress((void**)&kt, g_kt);

    // Stage 0: x transpose (for V projection)
    {
        dim3 grid(NPIX / 32, CH / 32, BATCH);
        transpose_kernel<<<grid, 256>>>(x);
    }
    // Stage 1: projections
    {
        dim3 gridqk(NPIX / 64, 1, BATCH);
        proj_qk_kernel<<<gridqk, 256>>>(Wq, bq, x, qt);
        proj_qk_kernel<<<gridqk, 256>>>(Wk, bk, x, kt);
        dim3 gridv(NPIX / 128, CH / 128, BATCH);
        projv_mma_kernel<<<gridv, 256>>>(Wv, bv);
    }
    // Stage 2: scores
    {
        dim3 grid(NPIX / 128, NPIX / 128, BATCH);
        scores_mma_kernel<<<grid, 256>>>();
    }
    // Stage 3: softmax
    softmax_kernel<<<BATCH * NPIX, 256>>>();
    // Stage 4: PV + epilogue
    {
        dim3 grid(NPIX / 128, CH / 128, BATCH);
        pv_mma_kernel<<<grid, 256>>>(x, gamma, out);
    }
}

// round 7
// speedup vs baseline: 4.8104x; 1.4121x over previous
#include <cuda_runtime.h>
#include <math.h>
#include <stdint.h>

#define BATCH 2
#define CH    512
#define DQK   64
#define NPIX  4096   // 64*64

// ---- scratch (allocation-free: __device__ globals) ----
__device__ __align__(16) float g_qt[(size_t)BATCH * NPIX * DQK];   // [b, n, d]   2 MB
__device__ __align__(16) float g_kt[(size_t)BATCH * NPIX * DQK];   // [b, n, d]   2 MB
__device__ __align__(16) float g_v [(size_t)BATCH * CH  * NPIX];   // [b, c, n]  16 MB
__device__ __align__(16) float g_xt[(size_t)BATCH * NPIX * CH];    // [b, n, c]  16 MB
__device__ __align__(16) float g_p [(size_t)BATCH * NPIX * NPIX];  // [b, i, j] 128 MB

// ============================================================
// mma helpers
// ============================================================
__device__ __forceinline__ void ldm_x4(uint32_t& r0, uint32_t& r1, uint32_t& r2, uint32_t& r3,
                                       uint32_t addr) {
    asm volatile("ldmatrix.sync.aligned.m8n8.x4.shared.b16 {%0,%1,%2,%3}, [%4];"
                 : "=r"(r0), "=r"(r1), "=r"(r2), "=r"(r3) : "r"(addr));
}

__device__ __forceinline__ void mma_tf32(float& c0, float& c1, float& c2, float& c3,
                                         uint32_t a0, uint32_t a1, uint32_t a2, uint32_t a3,
                                         uint32_t b0, uint32_t b1) {
    asm volatile(
        "mma.sync.aligned.m16n8k8.row.col.f32.tf32.tf32.f32 "
        "{%0,%1,%2,%3}, {%4,%5,%6,%7}, {%8,%9}, {%0,%1,%2,%3};"
        : "+f"(c0), "+f"(c1), "+f"(c2), "+f"(c3)
        : "r"(a0), "r"(a1), "r"(a2), "r"(a3), "r"(b0), "r"(b1));
}

__device__ __forceinline__ void cp_async16(uint32_t saddr, const void* gptr) {
    asm volatile("cp.async.cg.shared.global [%0], [%1], 16;" :: "r"(saddr), "l"(gptr));
}

// ============================================================
// Generic NT tf32 mainloop, cp.async double-buffered.
// C[128,128] += A[128,K] * B[128,K]^T (fp32 in gmem, HW-truncated to tf32)
// Dynamic smem: A stages [0,32KB), B stages [32KB,64KB). 16KB per stage.
// 256 threads, 8 warps (2x4), warp tile 64x32, K-tile 32.
// ============================================================
template<int K_TOTAL>
__device__ __forceinline__ void nt_mma_mainloop(
    const float* __restrict__ A, int lda,
    const float* __restrict__ B, int ldb,
    float (&acc)[4][4][4])
{
    extern __shared__ uint32_t smem_u32[];
    const uint32_t smem_base = (uint32_t)__cvta_generic_to_shared(smem_u32);
    const uint32_t As_base = smem_base;
    const uint32_t Bs_base = smem_base + 32768;

    const int tid  = threadIdx.x;
    const int lane = tid & 31;
    const int warp_m = (tid >> 5) >> 2;
    const int warp_n = (tid >> 5) & 3;
    const int lt = lane >> 3;
    const int lr = lane & 7;
    const int a_row_local = warp_m * 64 + (lt & 1) * 8 + lr;
    const int b_row_local = warp_n * 32 + (lt >> 1) * 8 + lr;

    constexpr int KT = K_TOTAL / 32;

    // stage loader: 4 float4 per thread per operand, swizzled dst
    #define ISSUE_STAGE(stage, k0)                                                 \
        {                                                                          \
            _Pragma("unroll")                                                      \
            for (int it = 0; it < 4; it++) {                                       \
                int t4  = it * 256 + tid;                                          \
                int row = t4 >> 3;                                                 \
                int c4  = t4 & 7;                                                  \
                uint32_t soff = (uint32_t)((stage) * 16384 +                       \
                                (((row << 3) + (c4 ^ (row & 7))) << 4));           \
                cp_async16(As_base + soff, A + (size_t)row * lda + (k0) + c4 * 4); \
                cp_async16(Bs_base + soff, B + (size_t)row * ldb + (k0) + c4 * 4); \
            }                                                                      \
            asm volatile("cp.async.commit_group;" ::: "memory");                   \
        }

    ISSUE_STAGE(0, 0);

    for (int kt = 0; kt < KT; kt++) {
        if (kt + 1 < KT) {
            ISSUE_STAGE((kt + 1) & 1, (kt + 1) * 32);
            asm volatile("cp.async.wait_group 1;" ::: "memory");
        } else {
            asm volatile("cp.async.wait_group 0;" ::: "memory");
        }
        __syncthreads();

        const uint32_t a_st = As_base + (kt & 1) * 16384;
        const uint32_t b_st = Bs_base + (kt & 1) * 16384;

        #pragma unroll
        for (int ks = 0; ks < 4; ks++) {
            uint32_t bfr[4][2];
            #pragma unroll
            for (int np = 0; np < 2; np++) {
                int row = b_row_local + np * 16;
                int c4  = ks * 2 + (lt & 1);
                uint32_t addr = b_st + (uint32_t)(((row << 3) + (c4 ^ (row & 7))) << 4);
                ldm_x4(bfr[np * 2][0], bfr[np * 2][1], bfr[np * 2 + 1][0], bfr[np * 2 + 1][1], addr);
            }
            #pragma unroll
            for (int mt = 0; mt < 4; mt++) {
                int row = a_row_local + mt * 16;
                int c4  = ks * 2 + (lt >> 1);
                uint32_t addr = a_st + (uint32_t)(((row << 3) + (c4 ^ (row & 7))) << 4);
                uint32_t a0, a1, a2, a3;
                ldm_x4(a0, a1, a2, a3, addr);
                #pragma unroll
                for (int nt = 0; nt < 4; nt++)
                    mma_tf32(acc[mt][nt][0], acc[mt][nt][1], acc[mt][nt][2], acc[mt][nt][3],
                             a0, a1, a2, a3, bfr[nt][0], bfr[nt][1]);
            }
        }
        __syncthreads();   // protect stage (kt+1)&1 before next overwrite
    }
    #undef ISSUE_STAGE
}

#define MMA_SMEM_BYTES 65536

// ============================================================
// Stage 0: transpose x[b,c,n] -> xt[b,n,c]
// ============================================================
__global__ __launch_bounds__(256) void transpose_kernel(const float* __restrict__ x)
{
    __shared__ float tile[32][33];
    const int b  = blockIdx.z;
    const int n0 = blockIdx.x * 32;
    const int c0 = blockIdx.y * 32;
    const int tx = threadIdx.x & 31;
    const int ty = threadIdx.x >> 5;

    const float* X = x + (size_t)b * CH * NPIX;
    float* XT = g_xt + (size_t)b * NPIX * CH;

    #pragma unroll
    for (int r = 0; r < 4; r++) {
        int c = ty + r * 8;
        tile[c][tx] = X[(size_t)(c0 + c) * NPIX + n0 + tx];
    }
    __syncthreads();
    #pragma unroll
    for (int r = 0; r < 4; r++) {
        int n = ty + r * 8;
        XT[(size_t)(n0 + n) * CH + c0 + tx] = tile[tx][n];
    }
}

// ============================================================
// Stage 1a: merged Q+K projection (fp32 SIMT, precision-critical).
// One X tile feeds both weight blocks; writes transposed qt/kt.
// ============================================================
__global__ __launch_bounds__(256) void proj_qk2_kernel(
    const float* __restrict__ Wq, const float* __restrict__ bq,
    const float* __restrict__ Wk, const float* __restrict__ bk,
    const float* __restrict__ x)
{
    const int b  = blockIdx.y;
    const int n0 = blockIdx.x * 64;
    const float* X = x + (size_t)b * CH * NPIX;

    __shared__ float Ws[16][129];   // [k][m]: m 0-63 = Wq rows, 64-127 = Wk rows
    __shared__ float Xs[16][64];
    __shared__ float Os[64][65];

    const int tid = threadIdx.x;
    const int tm = (tid >> 4) << 2;
    const int tn = (tid & 15) << 2;

    float accq[4][4] = {};
    float acck[4][4] = {};

    for (int k0 = 0; k0 < CH; k0 += 16) {
        #pragma unroll
        for (int t = tid; t < 128 * 16; t += 256) {
            int m  = t >> 4;
            int kk = t & 15;
            Ws[kk][m] = (m < 64) ? Wq[(size_t)m * CH + k0 + kk]
                                 : Wk[(size_t)(m - 64) * CH + k0 + kk];
        }
        #pragma unroll
        for (int t = tid; t < 16 * 64; t += 256) {
            int kk = t >> 6;
            int n  = t & 63;
            Xs[kk][n] = X[(size_t)(k0 + kk) * NPIX + n0 + n];
        }
        __syncthreads();
        #pragma unroll
        for (int kk = 0; kk < 16; kk++) {
            float aq[4], ak[4], bb[4];
            #pragma unroll
            for (int u = 0; u < 4; u++) aq[u] = Ws[kk][tm + u];
            #pragma unroll
            for (int u = 0; u < 4; u++) ak[u] = Ws[kk][64 + tm + u];
            #pragma unroll
            for (int u = 0; u < 4; u++) bb[u] = Xs[kk][tn + u];
            #pragma unroll
            for (int u = 0; u < 4; u++)
                #pragma unroll
                for (int v = 0; v < 4; v++) {
                    accq[u][v] = fmaf(aq[u], bb[v], accq[u][v]);
                    acck[u][v] = fmaf(ak[u], bb[v], acck[u][v]);
                }
        }
        __syncthreads();
    }

    const int n_local = tid >> 2;
    const int m_base  = (tid & 3) * 16;

    // ---- q ----
    #pragma unroll
    for (int u = 0; u < 4; u++) {
        float bv = bq[tm + u];
        #pragma unroll
        for (int v = 0; v < 4; v++) Os[tm + u][tn + v] = accq[u][v] + bv;
    }
    __syncthreads();
    {
        float* OT = g_qt + (size_t)b * NPIX * DQK;
        #pragma unroll
        for (int j = 0; j < 4; j++) {
            int m = m_base + j * 4;
            float4 vv;
            vv.x = Os[m + 0][n_local];
            vv.y = Os[m + 1][n_local];
            vv.z = Os[m + 2][n_local];
            vv.w = Os[m + 3][n_local];
            *reinterpret_cast<float4*>(OT + (size_t)(n0 + n_local) * DQK + m) = vv;
        }
    }
    __syncthreads();

    // ---- k ----
    #pragma unroll
    for (int u = 0; u < 4; u++) {
        float bv = bk[tm + u];
        #pragma unroll
        for (int v = 0; v < 4; v++) Os[tm + u][tn + v] = acck[u][v] + bv;
    }
    __syncthreads();
    {
        float* OT = g_kt + (size_t)b * NPIX * DQK;
        #pragma unroll
        for (int j = 0; j < 4; j++) {
            int m = m_base + j * 4;
            float4 vv;
            vv.x = Os[m + 0][n_local];
            vv.y = Os[m + 1][n_local];
            vv.z = Os[m + 2][n_local];
            vv.w = Os[m + 3][n_local];
            *reinterpret_cast<float4*>(OT + (size_t)(n0 + n_local) * DQK + m) = vv;
        }
    }
}

// ============================================================
// Stage 1b: V projection, tf32 mma.
// ============================================================
__global__ __launch_bounds__(256, 2) void projv_mma_kernel(
    const float* __restrict__ Wv, const float* __restrict__ bv)
{
    const int b  = blockIdx.z;
    const int m0 = blockIdx.y * 128;
    const int n0 = blockIdx.x * 128;

    const float* A = Wv + (size_t)m0 * CH;
    const float* B = g_xt + ((size_t)b * NPIX + n0) * CH;

    float acc[4][4][4] = {};
    nt_mma_mainloop<CH>(A, CH, B, CH, acc);

    const int tid  = threadIdx.x;
    const int lane = tid & 31;
    const int warp_m = (tid >> 5) >> 2;
    const int warp_n = (tid >> 5) & 3;
    const int gq = lane >> 2;
    const int qc = (lane & 3) * 2;

    float* Vb = g_v + (size_t)b * CH * NPIX;
    #pragma unroll
    for (int mt = 0; mt < 4; mt++) {
        int m_base = m0 + warp_m * 64 + mt * 16;
        #pragma unroll
        for (int nt = 0; nt < 4; nt++) {
            int n_base = n0 + warp_n * 32 + nt * 8;
            #pragma unroll
            for (int h = 0; h < 2; h++) {
                int m = m_base + gq + h * 8;
                float bias = bv[m];
                float2 ov;
                ov.x = acc[mt][nt][h * 2 + 0] + bias;
                ov.y = acc[mt][nt][h * 2 + 1] + bias;
                *reinterpret_cast<float2*>(Vb + (size_t)m * NPIX + n_base + qc) = ov;
            }
        }
    }
}

// ============================================================
// Stage 2: scores, tf32 mma.
// ============================================================
__global__ __launch_bounds__(256, 2) void scores_mma_kernel()
{
    const int b  = blockIdx.z;
    const int i0 = blockIdx.y * 128;
    const int j0 = blockIdx.x * 128;

    const float* A = g_qt + ((size_t)b * NPIX + i0) * DQK;
    const float* B = g_kt + ((size_t)b * NPIX + j0) * DQK;

    float acc[4][4][4] = {};
    nt_mma_mainloop<DQK>(A, DQK, B, DQK, acc);

    const int tid  = threadIdx.x;
    const int lane = tid & 31;
    const int warp_m = (tid >> 5) >> 2;
    const int warp_n = (tid >> 5) & 3;
    const int gq = lane >> 2;
    const int qc = (lane & 3) * 2;

    float* S = g_p + (size_t)b * NPIX * NPIX;
    #pragma unroll
    for (int mt = 0; mt < 4; mt++) {
        int i_base = i0 + warp_m * 64 + mt * 16;
        #pragma unroll
        for (int nt = 0; nt < 4; nt++) {
            int j_base = j0 + warp_n * 32 + nt * 8;
            #pragma unroll
            for (int h = 0; h < 2; h++) {
                float2 ov;
                ov.x = acc[mt][nt][h * 2 + 0];
                ov.y = acc[mt][nt][h * 2 + 1];
                *reinterpret_cast<float2*>(S + (size_t)(i_base + gq + h * 8) * NPIX + j_base + qc) = ov;
            }
        }
    }
}

// ============================================================
// Stage 3: softmax (row-resident in registers)
// ============================================================
__global__ __launch_bounds__(256) void softmax_kernel()
{
    const size_t row = blockIdx.x;
    float* S = g_p + row * NPIX;
    const int tid = threadIdx.x;

    float4 vals[4];
    float m = -1e30f;
    #pragma unroll
    for (int t = 0; t < 4; t++) {
        vals[t] = reinterpret_cast<float4*>(S)[tid + t * 256];
        m = fmaxf(m, fmaxf(fmaxf(vals[t].x, vals[t].y), fmaxf(vals[t].z, vals[t].w)));
    }

    __shared__ float red[8];
    #pragma unroll
    for (int o = 16; o; o >>= 1) m = fmaxf(m, __shfl_xor_sync(0xffffffffu, m, o));
    if ((tid & 31) == 0) red[tid >> 5] = m;
    __syncthreads();
    m = red[0];
    #pragma unroll
    for (int w = 1; w < 8; w++) m = fmaxf(m, red[w]);
    __syncthreads();

    float l = 0.f;
    #pragma unroll
    for (int t = 0; t < 4; t++) {
        vals[t].x = __expf(vals[t].x - m);
        vals[t].y = __expf(vals[t].y - m);
        vals[t].z = __expf(vals[t].z - m);
        vals[t].w = __expf(vals[t].w - m);
        l += (vals[t].x + vals[t].y) + (vals[t].z + vals[t].w);
    }
    #pragma unroll
    for (int o = 16; o; o >>= 1) l += __shfl_xor_sync(0xffffffffu, l, o);
    if ((tid & 31) == 0) red[tid >> 5] = l;
    __syncthreads();
    l = 0.f;
    #pragma unroll
    for (int w = 0; w < 8; w++) l += red[w];

    const float inv = 1.0f / l;
    #pragma unroll
    for (int t = 0; t < 4; t++) {
        vals[t].x *= inv; vals[t].y *= inv; vals[t].z *= inv; vals[t].w *= inv;
        reinterpret_cast<float4*>(S)[tid + t * 256] = vals[t];
    }
}

// ============================================================
// Stage 4: PV, tf32 mma.  out = gamma * (V P^T) + x
// ============================================================
__global__ __launch_bounds__(256, 2) void pv_mma_kernel(
    const float* __restrict__ x, const float* __restrict__ gamma_p,
    float* __restrict__ out)
{
    const int b  = blockIdx.z;
    const int c0 = blockIdx.y * 128;
    const int i0 = blockIdx.x * 128;

    const float* A = g_v + (size_t)b * CH * NPIX + (size_t)c0 * NPIX;
    const float* B = g_p + (size_t)b * NPIX * NPIX + (size_t)i0 * NPIX;

    float acc[4][4][4] = {};
    nt_mma_mainloop<NPIX>(A, NPIX, B, NPIX, acc);

    const int tid  = threadIdx.x;
    const int lane = tid & 31;
    const int warp_m = (tid >> 5) >> 2;
    const int warp_n = (tid >> 5) & 3;
    const int gq = lane >> 2;
    const int qc = (lane & 3) * 2;

    const float g = *gamma_p;
    const float* Xb = x   + (size_t)b * CH * NPIX;
    float*       Ob = out + (size_t)b * CH * NPIX;

    #pragma unroll
    for (int mt = 0; mt < 4; mt++) {
        int c_base = c0 + warp_m * 64 + mt * 16;
        #pragma unroll
        for (int nt = 0; nt < 4; nt++) {
            int i_base = i0 + warp_n * 32 + nt * 8;
            #pragma unroll
            for (int h = 0; h < 2; h++) {
                size_t idx = (size_t)(c_base + gq + h * 8) * NPIX + i_base + qc;
                float2 xv = *reinterpret_cast<const float2*>(Xb + idx);
                float2 ov;
                ov.x = fmaf(g, acc[mt][nt][h * 2 + 0], xv.x);
                ov.y = fmaf(g, acc[mt][nt][h * 2 + 1], xv.y);
                *reinterpret_cast<float2*>(Ob + idx) = ov;
            }
        }
    }
}

// ============================================================
// launch
// ============================================================
extern "C" void kernel_launch(void* const* d_in, const int* in_sizes, int n_in,
                              void* d_out, int out_size)
{
    const float* x     = (const float*)d_in[0];
    const float* Wq    = (const float*)d_in[1];
    const float* bq    = (const float*)d_in[2];
    const float* Wk    = (const float*)d_in[3];
    const float* bk    = (const float*)d_in[4];
    const float* Wv    = (const float*)d_in[5];
    const float* bv    = (const float*)d_in[6];
    const float* gamma = (const float*)d_in[7];
    float* out = (float*)d_out;

    // opt-in to 64KB dynamic smem for the mma kernels (host-side attr, idempotent)
    cudaFuncSetAttribute(projv_mma_kernel,  cudaFuncAttributeMaxDynamicSharedMemorySize, MMA_SMEM_BYTES);
    cudaFuncSetAttribute(scores_mma_kernel, cudaFuncAttributeMaxDynamicSharedMemorySize, MMA_SMEM_BYTES);
    cudaFuncSetAttribute(pv_mma_kernel,     cudaFuncAttributeMaxDynamicSharedMemorySize, MMA_SMEM_BYTES);

    // Stage 0: x transpose (feeds V projection)
    {
        dim3 grid(NPIX / 32, CH / 32, BATCH);
        transpose_kernel<<<grid, 256>>>(x);
    }
    // Stage 1: projections
    {
        dim3 gridqk(NPIX / 64, BATCH);
        proj_qk2_kernel<<<gridqk, 256>>>(Wq, bq, Wk, bk, x);
        dim3 gridv(NPIX / 128, CH / 128, BATCH);
        projv_mma_kernel<<<gridv, 256, MMA_SMEM_BYTES>>>(Wv, bv);
    }
    // Stage 2: scores
    {
        dim3 grid(NPIX / 128, NPIX / 128, BATCH);
        scores_mma_kernel<<<grid, 256, MMA_SMEM_BYTES>>>();
    }
    // Stage 3: softmax
    softmax_kernel<<<BATCH * NPIX, 256>>>();
    // Stage 4: PV + epilogue
    {
        dim3 grid(NPIX / 128, CH / 128, BATCH);
        pv_mma_kernel<<<grid, 256, MMA_SMEM_BYTES>>>(x, gamma, out);
    }
}

// round 10
// speedup vs baseline: 6.6579x; 1.3841x over previous
#include <cuda_runtime.h>
#include <cuda_fp16.h>
#include <math.h>
#include <stdint.h>

#define BATCH 2
#define CH    512
#define DQK   64
#define NPIX  4096   // 64*64

// ---- scratch (allocation-free: __device__ globals) ----
__device__ __align__(16) float  g_qt[(size_t)BATCH * NPIX * DQK];   // [b, n, d]   2 MB
__device__ __align__(16) float  g_kt[(size_t)BATCH * NPIX * DQK];   // [b, n, d]   2 MB
__device__ __align__(16) __half g_vh[(size_t)BATCH * CH  * NPIX];   // [b, c, n]   8 MB fp16
__device__ __align__(16) float  g_xt[(size_t)BATCH * NPIX * CH];    // [b, n, c]  16 MB
__device__ __align__(16) float  g_p [(size_t)BATCH * NPIX * NPIX];  // [b, i, j] 128 MB fp32 scores
__device__ __align__(16) __half g_ph[(size_t)BATCH * NPIX * NPIX];  // [b, i, j]  64 MB fp16 probs

// ============================================================
// mma helpers
// ============================================================
__device__ __forceinline__ void ldm_x4(uint32_t& r0, uint32_t& r1, uint32_t& r2, uint32_t& r3,
                                       uint32_t addr) {
    asm volatile("ldmatrix.sync.aligned.m8n8.x4.shared.b16 {%0,%1,%2,%3}, [%4];"
                 : "=r"(r0), "=r"(r1), "=r"(r2), "=r"(r3) : "r"(addr));
}

__device__ __forceinline__ void mma_tf32(float& c0, float& c1, float& c2, float& c3,
                                         uint32_t a0, uint32_t a1, uint32_t a2, uint32_t a3,
                                         uint32_t b0, uint32_t b1) {
    asm volatile(
        "mma.sync.aligned.m16n8k8.row.col.f32.tf32.tf32.f32 "
        "{%0,%1,%2,%3}, {%4,%5,%6,%7}, {%8,%9}, {%0,%1,%2,%3};"
        : "+f"(c0), "+f"(c1), "+f"(c2), "+f"(c3)
        : "r"(a0), "r"(a1), "r"(a2), "r"(a3), "r"(b0), "r"(b1));
}

__device__ __forceinline__ void mma_f16(float& c0, float& c1, float& c2, float& c3,
                                        uint32_t a0, uint32_t a1, uint32_t a2, uint32_t a3,
                                        uint32_t b0, uint32_t b1) {
    asm volatile(
        "mma.sync.aligned.m16n8k16.row.col.f32.f16.f16.f32 "
        "{%0,%1,%2,%3}, {%4,%5,%6,%7}, {%8,%9}, {%0,%1,%2,%3};"
        : "+f"(c0), "+f"(c1), "+f"(c2), "+f"(c3)
        : "r"(a0), "r"(a1), "r"(a2), "r"(a3), "r"(b0), "r"(b1));
}

__device__ __forceinline__ void cp_async16(uint32_t saddr, const void* gptr) {
    asm volatile("cp.async.cg.shared.global [%0], [%1], 16;" :: "r"(saddr), "l"(gptr));
}

// ============================================================
// tf32 NT mainloop, cp.async double-buffered (validated R7).
// K-tile 32 fp32; 16KB/operand/stage; stages A:[0,32K) B:[32K,64K).
// ============================================================
template<int K_TOTAL>
__device__ __forceinline__ void nt_mma_mainloop(
    const float* __restrict__ A, int lda,
    const float* __restrict__ B, int ldb,
    float (&acc)[4][4][4])
{
    extern __shared__ uint32_t smem_u32[];
    const uint32_t smem_base = (uint32_t)__cvta_generic_to_shared(smem_u32);
    const uint32_t As_base = smem_base;
    const uint32_t Bs_base = smem_base + 32768;

    const int tid  = threadIdx.x;
    const int lane = tid & 31;
    const int warp_m = (tid >> 5) >> 2;
    const int warp_n = (tid >> 5) & 3;
    const int lt = lane >> 3;
    const int lr = lane & 7;
    const int a_row_local = warp_m * 64 + (lt & 1) * 8 + lr;
    const int b_row_local = warp_n * 32 + (lt >> 1) * 8 + lr;

    constexpr int KT = K_TOTAL / 32;

    #define ISSUE_STAGE_F32(stage, k0)                                             \
        {                                                                          \
            _Pragma("unroll")                                                      \
            for (int it = 0; it < 4; it++) {                                       \
                int t4  = it * 256 + tid;                                          \
                int row = t4 >> 3;                                                 \
                int c4  = t4 & 7;                                                  \
                uint32_t soff = (uint32_t)((stage) * 16384 +                       \
                                (((row << 3) + (c4 ^ (row & 7))) << 4));           \
                cp_async16(As_base + soff, A + (size_t)row * lda + (k0) + c4 * 4); \
                cp_async16(Bs_base + soff, B + (size_t)row * ldb + (k0) + c4 * 4); \
            }                                                                      \
            asm volatile("cp.async.commit_group;" ::: "memory");                   \
        }

    ISSUE_STAGE_F32(0, 0);

    for (int kt = 0; kt < KT; kt++) {
        if (kt + 1 < KT) {
            ISSUE_STAGE_F32((kt + 1) & 1, (kt + 1) * 32);
            asm volatile("cp.async.wait_group 1;" ::: "memory");
        } else {
            asm volatile("cp.async.wait_group 0;" ::: "memory");
        }
        __syncthreads();

        const uint32_t a_st = As_base + (kt & 1) * 16384;
        const uint32_t b_st = Bs_base + (kt & 1) * 16384;

        #pragma unroll
        for (int ks = 0; ks < 4; ks++) {
            uint32_t bfr[4][2];
            #pragma unroll
            for (int np = 0; np < 2; np++) {
                int row = b_row_local + np * 16;
                int c4  = ks * 2 + (lt & 1);
                uint32_t addr = b_st + (uint32_t)(((row << 3) + (c4 ^ (row & 7))) << 4);
                ldm_x4(bfr[np * 2][0], bfr[np * 2][1], bfr[np * 2 + 1][0], bfr[np * 2 + 1][1], addr);
            }
            #pragma unroll
            for (int mt = 0; mt < 4; mt++) {
                int row = a_row_local + mt * 16;
                int c4  = ks * 2 + (lt >> 1);
                uint32_t addr = a_st + (uint32_t)(((row << 3) + (c4 ^ (row & 7))) << 4);
                uint32_t a0, a1, a2, a3;
                ldm_x4(a0, a1, a2, a3, addr);
                #pragma unroll
                for (int nt = 0; nt < 4; nt++)
                    mma_tf32(acc[mt][nt][0], acc[mt][nt][1], acc[mt][nt][2], acc[mt][nt][3],
                             a0, a1, a2, a3, bfr[nt][0], bfr[nt][1]);
            }
        }
        __syncthreads();
    }
    #undef ISSUE_STAGE_F32
}

// ============================================================
// fp16 NT mainloop, cp.async double-buffered.
// Same structure; K-tile 64 halfs (=128B/row = 8x16B chunks, identical
// swizzle/addressing; each 16B chunk = 8 halfs). m16n8k16, fp32 accum.
// ============================================================
template<int K_TOTAL>
__device__ __forceinline__ void nt_mma_mainloop_f16(
    const __half* __restrict__ A, int lda,
    const __half* __restrict__ B, int ldb,
    float (&acc)[4][4][4])
{
    extern __shared__ uint32_t smem_u32[];
    const uint32_t smem_base = (uint32_t)__cvta_generic_to_shared(smem_u32);
    const uint32_t As_base = smem_base;
    const uint32_t Bs_base = smem_base + 32768;

    const int tid  = threadIdx.x;
    const int lane = tid & 31;
    const int warp_m = (tid >> 5) >> 2;
    const int warp_n = (tid >> 5) & 3;
    const int lt = lane >> 3;
    const int lr = lane & 7;
    const int a_row_local = warp_m * 64 + (lt & 1) * 8 + lr;
    const int b_row_local = warp_n * 32 + (lt >> 1) * 8 + lr;

    constexpr int KT = K_TOTAL / 64;

    #define ISSUE_STAGE_F16(stage, k0)                                             \
        {                                                                          \
            _Pragma("unroll")                                                      \
            for (int it = 0; it < 4; it++) {                                       \
                int t4  = it * 256 + tid;                                          \
                int row = t4 >> 3;                                                 \
                int c4  = t4 & 7;                                                  \
                uint32_t soff = (uint32_t)((stage) * 16384 +                       \
                                (((row << 3) + (c4 ^ (row & 7))) << 4));           \
                cp_async16(As_base + soff, A + (size_t)row * lda + (k0) + c4 * 8); \
                cp_async16(Bs_base + soff, B + (size_t)row * ldb + (k0) + c4 * 8); \
            }                                                                      \
            asm volatile("cp.async.commit_group;" ::: "memory");                   \
        }

    ISSUE_STAGE_F16(0, 0);

    for (int kt = 0; kt < KT; kt++) {
        if (kt + 1 < KT) {
            ISSUE_STAGE_F16((kt + 1) & 1, (kt + 1) * 64);
            asm volatile("cp.async.wait_group 1;" ::: "memory");
        } else {
            asm volatile("cp.async.wait_group 0;" ::: "memory");
        }
        __syncthreads();

        const uint32_t a_st = As_base + (kt & 1) * 16384;
        const uint32_t b_st = Bs_base + (kt & 1) * 16384;

        // 4 ks iters, each m16n8k16 (k = ks*16 .. +15 = chunks ks*2, ks*2+1)
        #pragma unroll
        for (int ks = 0; ks < 4; ks++) {
            uint32_t bfr[4][2];
            #pragma unroll
            for (int np = 0; np < 2; np++) {
                int row = b_row_local + np * 16;
                int c4  = ks * 2 + (lt & 1);
                uint32_t addr = b_st + (uint32_t)(((row << 3) + (c4 ^ (row & 7))) << 4);
                ldm_x4(bfr[np * 2][0], bfr[np * 2][1], bfr[np * 2 + 1][0], bfr[np * 2 + 1][1], addr);
            }
            #pragma unroll
            for (int mt = 0; mt < 4; mt++) {
                int row = a_row_local + mt * 16;
                int c4  = ks * 2 + (lt >> 1);
                uint32_t addr = a_st + (uint32_t)(((row << 3) + (c4 ^ (row & 7))) << 4);
                uint32_t a0, a1, a2, a3;
                ldm_x4(a0, a1, a2, a3, addr);
                #pragma unroll
                for (int nt = 0; nt < 4; nt++)
                    mma_f16(acc[mt][nt][0], acc[mt][nt][1], acc[mt][nt][2], acc[mt][nt][3],
                            a0, a1, a2, a3, bfr[nt][0], bfr[nt][1]);
            }
        }
        __syncthreads();
    }
    #undef ISSUE_STAGE_F16
}

#define MMA_SMEM_BYTES 65536

// ============================================================
// Stage 0: transpose x[b,c,n] -> xt[b,n,c]
// ============================================================
__global__ __launch_bounds__(256) void transpose_kernel(const float* __restrict__ x)
{
    __shared__ float tile[32][33];
    const int b  = blockIdx.z;
    const int n0 = blockIdx.x * 32;
    const int c0 = blockIdx.y * 32;
    const int tx = threadIdx.x & 31;
    const int ty = threadIdx.x >> 5;

    const float* X = x + (size_t)b * CH * NPIX;
    float* XT = g_xt + (size_t)b * NPIX * CH;

    #pragma unroll
    for (int r = 0; r < 4; r++) {
        int c = ty + r * 8;
        tile[c][tx] = X[(size_t)(c0 + c) * NPIX + n0 + tx];
    }
    __syncthreads();
    #pragma unroll
    for (int r = 0; r < 4; r++) {
        int n = ty + r * 8;
        XT[(size_t)(n0 + n) * CH + c0 + tx] = tile[tx][n];
    }
}

// ============================================================
// Stage 1a: merged Q+K projection (fp32 SIMT, precision-critical).
// ============================================================
__global__ __launch_bounds__(256) void proj_qk2_kernel(
    const float* __restrict__ Wq, const float* __restrict__ bq,
    const float* __restrict__ Wk, const float* __restrict__ bk,
    const float* __restrict__ x)
{
    const int b  = blockIdx.y;
    const int n0 = blockIdx.x * 64;
    const float* X = x + (size_t)b * CH * NPIX;

    __shared__ float Ws[16][129];
    __shared__ float Xs[16][64];
    __shared__ float Os[64][65];

    const int tid = threadIdx.x;
    const int tm = (tid >> 4) << 2;
    const int tn = (tid & 15) << 2;

    float accq[4][4] = {};
    float acck[4][4] = {};

    for (int k0 = 0; k0 < CH; k0 += 16) {
        #pragma unroll
        for (int t = tid; t < 128 * 16; t += 256) {
            int m  = t >> 4;
            int kk = t & 15;
            Ws[kk][m] = (m < 64) ? Wq[(size_t)m * CH + k0 + kk]
                                 : Wk[(size_t)(m - 64) * CH + k0 + kk];
        }
        #pragma unroll
        for (int t = tid; t < 16 * 64; t += 256) {
            int kk = t >> 6;
            int n  = t & 63;
            Xs[kk][n] = X[(size_t)(k0 + kk) * NPIX + n0 + n];
        }
        __syncthreads();
        #pragma unroll
        for (int kk = 0; kk < 16; kk++) {
            float aq[4], ak[4], bb[4];
            #pragma unroll
            for (int u = 0; u < 4; u++) aq[u] = Ws[kk][tm + u];
            #pragma unroll
            for (int u = 0; u < 4; u++) ak[u] = Ws[kk][64 + tm + u];
            #pragma unroll
            for (int u = 0; u < 4; u++) bb[u] = Xs[kk][tn + u];
            #pragma unroll
            for (int u = 0; u < 4; u++)
                #pragma unroll
                for (int v = 0; v < 4; v++) {
                    accq[u][v] = fmaf(aq[u], bb[v], accq[u][v]);
                    acck[u][v] = fmaf(ak[u], bb[v], acck[u][v]);
                }
        }
        __syncthreads();
    }

    const int n_local = tid >> 2;
    const int m_base  = (tid & 3) * 16;

    // ---- q ----
    #pragma unroll
    for (int u = 0; u < 4; u++) {
        float bv = bq[tm + u];
        #pragma unroll
        for (int v = 0; v < 4; v++) Os[tm + u][tn + v] = accq[u][v] + bv;
    }
    __syncthreads();
    {
        float* OT = g_qt + (size_t)b * NPIX * DQK;
        #pragma unroll
        for (int j = 0; j < 4; j++) {
            int m = m_base + j * 4;
            float4 vv;
            vv.x = Os[m + 0][n_local];
            vv.y = Os[m + 1][n_local];
            vv.z = Os[m + 2][n_local];
            vv.w = Os[m + 3][n_local];
            *reinterpret_cast<float4*>(OT + (size_t)(n0 + n_local) * DQK + m) = vv;
        }
    }
    __syncthreads();

    // ---- k ----
    #pragma unroll
    for (int u = 0; u < 4; u++) {
        float bv = bk[tm + u];
        #pragma unroll
        for (int v = 0; v < 4; v++) Os[tm + u][tn + v] = acck[u][v] + bv;
    }
    __syncthreads();
    {
        float* OT = g_kt + (size_t)b * NPIX * DQK;
        #pragma unroll
        for (int j = 0; j < 4; j++) {
            int m = m_base + j * 4;
            float4 vv;
            vv.x = Os[m + 0][n_local];
            vv.y = Os[m + 1][n_local];
            vv.z = Os[m + 2][n_local];
            vv.w = Os[m + 3][n_local];
            *reinterpret_cast<float4*>(OT + (size_t)(n0 + n_local) * DQK + m) = vv;
        }
    }
}

// ============================================================
// Stage 1b: V projection, tf32 mma; writes fp16 V.
// ============================================================
__global__ __launch_bounds__(256, 2) void projv_mma_kernel(
    const float* __restrict__ Wv, const float* __restrict__ bv)
{
    const int b  = blockIdx.z;
    const int m0 = blockIdx.y * 128;
    const int n0 = blockIdx.x * 128;

    const float* A = Wv + (size_t)m0 * CH;
    const float* B = g_xt + ((size_t)b * NPIX + n0) * CH;

    float acc[4][4][4] = {};
    nt_mma_mainloop<CH>(A, CH, B, CH, acc);

    const int tid  = threadIdx.x;
    const int lane = tid & 31;
    const int warp_m = (tid >> 5) >> 2;
    const int warp_n = (tid >> 5) & 3;
    const int gq = lane >> 2;
    const int qc = (lane & 3) * 2;

    __half* Vb = g_vh + (size_t)b * CH * NPIX;
    #pragma unroll
    for (int mt = 0; mt < 4; mt++) {
        int m_base = m0 + warp_m * 64 + mt * 16;
        #pragma unroll
        for (int nt = 0; nt < 4; nt++) {
            int n_base = n0 + warp_n * 32 + nt * 8;
            #pragma unroll
            for (int h = 0; h < 2; h++) {
                int m = m_base + gq + h * 8;
                float bias = bv[m];
                __half2 hv = __floats2half2_rn(acc[mt][nt][h * 2 + 0] + bias,
                                               acc[mt][nt][h * 2 + 1] + bias);
                *reinterpret_cast<__half2*>(Vb + (size_t)m * NPIX + n_base + qc) = hv;
            }
        }
    }
}

// ============================================================
// Stage 2: scores, tf32 mma (fp32 output -- precision-critical).
// ============================================================
__global__ __launch_bounds__(256, 2) void scores_mma_kernel()
{
    const int b  = blockIdx.z;
    const int i0 = blockIdx.y * 128;
    const int j0 = blockIdx.x * 128;

    const float* A = g_qt + ((size_t)b * NPIX + i0) * DQK;
    const float* B = g_kt + ((size_t)b * NPIX + j0) * DQK;

    float acc[4][4][4] = {};
    nt_mma_mainloop<DQK>(A, DQK, B, DQK, acc);

    const int tid  = threadIdx.x;
    const int lane = tid & 31;
    const int warp_m = (tid >> 5) >> 2;
    const int warp_n = (tid >> 5) & 3;
    const int gq = lane >> 2;
    const int qc = (lane & 3) * 2;

    float* S = g_p + (size_t)b * NPIX * NPIX;
    #pragma unroll
    for (int mt = 0; mt < 4; mt++) {
        int i_base = i0 + warp_m * 64 + mt * 16;
        #pragma unroll
        for (int nt = 0; nt < 4; nt++) {
            int j_base = j0 + warp_n * 32 + nt * 8;
            #pragma unroll
            for (int h = 0; h < 2; h++) {
                float2 ov;
                ov.x = acc[mt][nt][h * 2 + 0];
                ov.y = acc[mt][nt][h * 2 + 1];
                *reinterpret_cast<float2*>(S + (size_t)(i_base + gq + h * 8) * NPIX + j_base + qc) = ov;
            }
        }
    }
}

// ============================================================
// Stage 3: softmax; reads fp32 S, writes fp16 P.
// ============================================================
__global__ __launch_bounds__(256) void softmax_kernel()
{
    const size_t row = blockIdx.x;
    const float* S = g_p  + row * NPIX;
    __half*      P = g_ph + row * NPIX;
    const int tid = threadIdx.x;

    float4 vals[4];
    float m = -1e30f;
    #pragma unroll
    for (int t = 0; t < 4; t++) {
        vals[t] = reinterpret_cast<const float4*>(S)[tid + t * 256];
        m = fmaxf(m, fmaxf(fmaxf(vals[t].x, vals[t].y), fmaxf(vals[t].z, vals[t].w)));
    }

    __shared__ float red[8];
    #pragma unroll
    for (int o = 16; o; o >>= 1) m = fmaxf(m, __shfl_xor_sync(0xffffffffu, m, o));
    if ((tid & 31) == 0) red[tid >> 5] = m;
    __syncthreads();
    m = red[0];
    #pragma unroll
    for (int w = 1; w < 8; w++) m = fmaxf(m, red[w]);
    __syncthreads();

    float l = 0.f;
    #pragma unroll
    for (int t = 0; t < 4; t++) {
        vals[t].x = __expf(vals[t].x - m);
        vals[t].y = __expf(vals[t].y - m);
        vals[t].z = __expf(vals[t].z - m);
        vals[t].w = __expf(vals[t].w - m);
        l += (vals[t].x + vals[t].y) + (vals[t].z + vals[t].w);
    }
    #pragma unroll
    for (int o = 16; o; o >>= 1) l += __shfl_xor_sync(0xffffffffu, l, o);
    if ((tid & 31) == 0) red[tid >> 5] = l;
    __syncthreads();
    l = 0.f;
    #pragma unroll
    for (int w = 0; w < 8; w++) l += red[w];

    const float inv = 1.0f / l;
    #pragma unroll
    for (int t = 0; t < 4; t++) {
        __half2 h0 = __floats2half2_rn(vals[t].x * inv, vals[t].y * inv);
        __half2 h1 = __floats2half2_rn(vals[t].z * inv, vals[t].w * inv);
        // 8-byte store of 4 halfs at float4-slot position
        uint2 pk;
        pk.x = *reinterpret_cast<uint32_t*>(&h0);
        pk.y = *reinterpret_cast<uint32_t*>(&h1);
        reinterpret_cast<uint2*>(P)[tid + t * 256] = pk;
    }
}

// ============================================================
// Stage 4: PV, fp16 mma.  out = gamma * (V P^T) + x
// ============================================================
__global__ __launch_bounds__(256, 2) void pv_mma_kernel(
    const float* __restrict__ x, const float* __restrict__ gamma_p,
    float* __restrict__ out)
{
    const int b  = blockIdx.z;
    const int c0 = blockIdx.y * 128;
    const int i0 = blockIdx.x * 128;

    const __half* A = g_vh + (size_t)b * CH * NPIX + (size_t)c0 * NPIX;
    const __half* B = g_ph + (size_t)b * NPIX * NPIX + (size_t)i0 * NPIX;

    float acc[4][4][4] = {};
    nt_mma_mainloop_f16<NPIX>(A, NPIX, B, NPIX, acc);

    const int tid  = threadIdx.x;
    const int lane = tid & 31;
    const int warp_m = (tid >> 5) >> 2;
    const int warp_n = (tid >> 5) & 3;
    const int gq = lane >> 2;
    const int qc = (lane & 3) * 2;

    const float g = *gamma_p;
    const float* Xb = x   + (size_t)b * CH * NPIX;
    float*       Ob = out + (size_t)b * CH * NPIX;

    #pragma unroll
    for (int mt = 0; mt < 4; mt++) {
        int c_base = c0 + warp_m * 64 + mt * 16;
        #pragma unroll
        for (int nt = 0; nt < 4; nt++) {
            int i_base = i0 + warp_n * 32 + nt * 8;
            #pragma unroll
            for (int h = 0; h < 2; h++) {
                size_t idx = (size_t)(c_base + gq + h * 8) * NPIX + i_base + qc;
                float2 xv = *reinterpret_cast<const float2*>(Xb + idx);
                float2 ov;
                ov.x = fmaf(g, acc[mt][nt][h * 2 + 0], xv.x);
                ov.y = fmaf(g, acc[mt][nt][h * 2 + 1], xv.y);
                *reinterpret_cast<float2*>(Ob + idx) = ov;
            }
        }
    }
}

// ============================================================
// launch
// ============================================================
extern "C" void kernel_launch(void* const* d_in, const int* in_sizes, int n_in,
                              void* d_out, int out_size)
{
    const float* x     = (const float*)d_in[0];
    const float* Wq    = (const float*)d_in[1];
    const float* bq    = (const float*)d_in[2];
    const float* Wk    = (const float*)d_in[3];
    const float* bk    = (const float*)d_in[4];
    const float* Wv    = (const float*)d_in[5];
    const float* bv    = (const float*)d_in[6];
    const float* gamma = (const float*)d_in[7];
    float* out = (float*)d_out;

    cudaFuncSetAttribute(projv_mma_kernel,  cudaFuncAttributeMaxDynamicSharedMemorySize, MMA_SMEM_BYTES);
    cudaFuncSetAttribute(scores_mma_kernel, cudaFuncAttributeMaxDynamicSharedMemorySize, MMA_SMEM_BYTES);
    cudaFuncSetAttribute(pv_mma_kernel,     cudaFuncAttributeMaxDynamicSharedMemorySize, MMA_SMEM_BYTES);

    // Stage 0: x transpose (feeds V projection)
    {
        dim3 grid(NPIX / 32, CH / 32, BATCH);
        transpose_kernel<<<grid, 256>>>(x);
    }
    // Stage 1: projections
    {
        dim3 gridqk(NPIX / 64, BATCH);
        proj_qk2_kernel<<<gridqk, 256>>>(Wq, bq, Wk, bk, x);
        dim3 gridv(NPIX / 128, CH / 128, BATCH);
        projv_mma_kernel<<<gridv, 256, MMA_SMEM_BYTES>>>(Wv, bv);
    }
    // Stage 2: scores
    {
        dim3 grid(NPIX / 128, NPIX / 128, BATCH);
        scores_mma_kernel<<<grid, 256, MMA_SMEM_BYTES>>>();
    }
    // Stage 3: softmax (fp32 -> fp16)
    softmax_kernel<<<BATCH * NPIX, 256>>>();
    // Stage 4: PV (fp16) + epilogue
    {
        dim3 grid(NPIX / 128, CH / 128, BATCH);
        pv_mma_kernel<<<grid, 256, MMA_SMEM_BYTES>>>(x, gamma, out);
    }
}

// round 11
// speedup vs baseline: 7.7171x; 1.1591x over previous
#include <cuda_runtime.h>
#include <cuda_fp16.h>
#include <math.h>
#include <stdint.h>

#define BATCH 2
#define CH    512
#define DQK   64
#define NPIX  4096   // 64*64

// ---- scratch (allocation-free: __device__ globals) ----
__device__ __align__(16) float  g_qt [(size_t)BATCH * NPIX * DQK];   // [b, n, d]   2 MB
__device__ __align__(16) float  g_kt [(size_t)BATCH * NPIX * DQK];   // [b, n, d]   2 MB
__device__ __align__(16) __half g_vh [(size_t)BATCH * CH  * NPIX];   // [b, c, n]   8 MB fp16
__device__ __align__(16) float  g_xt [(size_t)BATCH * NPIX * CH];    // [b, n, c]  16 MB
__device__ __align__(16) float  g_wqk[(size_t)128 * CH];             // [Wq;Wk]   256 KB
__device__ __align__(16) float  g_p  [(size_t)BATCH * NPIX * NPIX];  // fp32 scores 128 MB
__device__ __align__(16) __half g_ph [(size_t)BATCH * NPIX * NPIX];  // fp16 probs   64 MB

// ============================================================
// mma helpers
// ============================================================
__device__ __forceinline__ void ldm_x4(uint32_t& r0, uint32_t& r1, uint32_t& r2, uint32_t& r3,
                                       uint32_t addr) {
    asm volatile("ldmatrix.sync.aligned.m8n8.x4.shared.b16 {%0,%1,%2,%3}, [%4];"
                 : "=r"(r0), "=r"(r1), "=r"(r2), "=r"(r3) : "r"(addr));
}

__device__ __forceinline__ void mma_tf32(float& c0, float& c1, float& c2, float& c3,
                                         uint32_t a0, uint32_t a1, uint32_t a2, uint32_t a3,
                                         uint32_t b0, uint32_t b1) {
    asm volatile(
        "mma.sync.aligned.m16n8k8.row.col.f32.tf32.tf32.f32 "
        "{%0,%1,%2,%3}, {%4,%5,%6,%7}, {%8,%9}, {%0,%1,%2,%3};"
        : "+f"(c0), "+f"(c1), "+f"(c2), "+f"(c3)
        : "r"(a0), "r"(a1), "r"(a2), "r"(a3), "r"(b0), "r"(b1));
}

__device__ __forceinline__ void mma_f16(float& c0, float& c1, float& c2, float& c3,
                                        uint32_t a0, uint32_t a1, uint32_t a2, uint32_t a3,
                                        uint32_t b0, uint32_t b1) {
    asm volatile(
        "mma.sync.aligned.m16n8k16.row.col.f32.f16.f16.f32 "
        "{%0,%1,%2,%3}, {%4,%5,%6,%7}, {%8,%9}, {%0,%1,%2,%3};"
        : "+f"(c0), "+f"(c1), "+f"(c2), "+f"(c3)
        : "r"(a0), "r"(a1), "r"(a2), "r"(a3), "r"(b0), "r"(b1));
}

__device__ __forceinline__ void cp_async16(uint32_t saddr, const void* gptr) {
    asm volatile("cp.async.cg.shared.global [%0], [%1], 16;" :: "r"(saddr), "l"(gptr));
}

// ============================================================
// tf32 NT mainloop, cp.async double-buffered (validated R7/R10).
// ============================================================
template<int K_TOTAL>
__device__ __forceinline__ void nt_mma_mainloop(
    const float* __restrict__ A, int lda,
    const float* __restrict__ B, int ldb,
    float (&acc)[4][4][4])
{
    extern __shared__ uint32_t smem_u32[];
    const uint32_t smem_base = (uint32_t)__cvta_generic_to_shared(smem_u32);
    const uint32_t As_base = smem_base;
    const uint32_t Bs_base = smem_base + 32768;

    const int tid  = threadIdx.x;
    const int lane = tid & 31;
    const int warp_m = (tid >> 5) >> 2;
    const int warp_n = (tid >> 5) & 3;
    const int lt = lane >> 3;
    const int lr = lane & 7;
    const int a_row_local = warp_m * 64 + (lt & 1) * 8 + lr;
    const int b_row_local = warp_n * 32 + (lt >> 1) * 8 + lr;

    constexpr int KT = K_TOTAL / 32;

    #define ISSUE_STAGE_F32(stage, k0)                                             \
        {                                                                          \
            _Pragma("unroll")                                                      \
            for (int it = 0; it < 4; it++) {                                       \
                int t4  = it * 256 + tid;                                          \
                int row = t4 >> 3;                                                 \
                int c4  = t4 & 7;                                                  \
                uint32_t soff = (uint32_t)((stage) * 16384 +                       \
                                (((row << 3) + (c4 ^ (row & 7))) << 4));           \
                cp_async16(As_base + soff, A + (size_t)row * lda + (k0) + c4 * 4); \
                cp_async16(Bs_base + soff, B + (size_t)row * ldb + (k0) + c4 * 4); \
            }                                                                      \
            asm volatile("cp.async.commit_group;" ::: "memory");                   \
        }

    ISSUE_STAGE_F32(0, 0);

    for (int kt = 0; kt < KT; kt++) {
        if (kt + 1 < KT) {
            ISSUE_STAGE_F32((kt + 1) & 1, (kt + 1) * 32);
            asm volatile("cp.async.wait_group 1;" ::: "memory");
        } else {
            asm volatile("cp.async.wait_group 0;" ::: "memory");
        }
        __syncthreads();

        const uint32_t a_st = As_base + (kt & 1) * 16384;
        const uint32_t b_st = Bs_base + (kt & 1) * 16384;

        #pragma unroll
        for (int ks = 0; ks < 4; ks++) {
            uint32_t bfr[4][2];
            #pragma unroll
            for (int np = 0; np < 2; np++) {
                int row = b_row_local + np * 16;
                int c4  = ks * 2 + (lt & 1);
                uint32_t addr = b_st + (uint32_t)(((row << 3) + (c4 ^ (row & 7))) << 4);
                ldm_x4(bfr[np * 2][0], bfr[np * 2][1], bfr[np * 2 + 1][0], bfr[np * 2 + 1][1], addr);
            }
            #pragma unroll
            for (int mt = 0; mt < 4; mt++) {
                int row = a_row_local + mt * 16;
                int c4  = ks * 2 + (lt >> 1);
                uint32_t addr = a_st + (uint32_t)(((row << 3) + (c4 ^ (row & 7))) << 4);
                uint32_t a0, a1, a2, a3;
                ldm_x4(a0, a1, a2, a3, addr);
                #pragma unroll
                for (int nt = 0; nt < 4; nt++)
                    mma_tf32(acc[mt][nt][0], acc[mt][nt][1], acc[mt][nt][2], acc[mt][nt][3],
                             a0, a1, a2, a3, bfr[nt][0], bfr[nt][1]);
            }
        }
        __syncthreads();
    }
    #undef ISSUE_STAGE_F32
}

// ============================================================
// fp16 NT mainloop, cp.async double-buffered (validated R10).
// ============================================================
template<int K_TOTAL>
__device__ __forceinline__ void nt_mma_mainloop_f16(
    const __half* __restrict__ A, int lda,
    const __half* __restrict__ B, int ldb,
    float (&acc)[4][4][4])
{
    extern __shared__ uint32_t smem_u32[];
    const uint32_t smem_base = (uint32_t)__cvta_generic_to_shared(smem_u32);
    const uint32_t As_base = smem_base;
    const uint32_t Bs_base = smem_base + 32768;

    const int tid  = threadIdx.x;
    const int lane = tid & 31;
    const int warp_m = (tid >> 5) >> 2;
    const int warp_n = (tid >> 5) & 3;
    const int lt = lane >> 3;
    const int lr = lane & 7;
    const int a_row_local = warp_m * 64 + (lt & 1) * 8 + lr;
    const int b_row_local = warp_n * 32 + (lt >> 1) * 8 + lr;

    constexpr int KT = K_TOTAL / 64;

    #define ISSUE_STAGE_F16(stage, k0)                                             \
        {                                                                          \
            _Pragma("unroll")                                                      \
            for (int it = 0; it < 4; it++) {                                       \
                int t4  = it * 256 + tid;                                          \
                int row = t4 >> 3;                                                 \
                int c4  = t4 & 7;                                                  \
                uint32_t soff = (uint32_t)((stage) * 16384 +                       \
                                (((row << 3) + (c4 ^ (row & 7))) << 4));           \
                cp_async16(As_base + soff, A + (size_t)row * lda + (k0) + c4 * 8); \
                cp_async16(Bs_base + soff, B + (size_t)row * ldb + (k0) + c4 * 8); \
            }                                                                      \
            asm volatile("cp.async.commit_group;" ::: "memory");                   \
        }

    ISSUE_STAGE_F16(0, 0);

    for (int kt = 0; kt < KT; kt++) {
        if (kt + 1 < KT) {
            ISSUE_STAGE_F16((kt + 1) & 1, (kt + 1) * 64);
            asm volatile("cp.async.wait_group 1;" ::: "memory");
        } else {
            asm volatile("cp.async.wait_group 0;" ::: "memory");
        }
        __syncthreads();

        const uint32_t a_st = As_base + (kt & 1) * 16384;
        const uint32_t b_st = Bs_base + (kt & 1) * 16384;

        #pragma unroll
        for (int ks = 0; ks < 4; ks++) {
            uint32_t bfr[4][2];
            #pragma unroll
            for (int np = 0; np < 2; np++) {
                int row = b_row_local + np * 16;
                int c4  = ks * 2 + (lt & 1);
                uint32_t addr = b_st + (uint32_t)(((row << 3) + (c4 ^ (row & 7))) << 4);
                ldm_x4(bfr[np * 2][0], bfr[np * 2][1], bfr[np * 2 + 1][0], bfr[np * 2 + 1][1], addr);
            }
            #pragma unroll
            for (int mt = 0; mt < 4; mt++) {
                int row = a_row_local + mt * 16;
                int c4  = ks * 2 + (lt >> 1);
                uint32_t addr = a_st + (uint32_t)(((row << 3) + (c4 ^ (row & 7))) << 4);
                uint32_t a0, a1, a2, a3;
                ldm_x4(a0, a1, a2, a3, addr);
                #pragma unroll
                for (int nt = 0; nt < 4; nt++)
                    mma_f16(acc[mt][nt][0], acc[mt][nt][1], acc[mt][nt][2], acc[mt][nt][3],
                            a0, a1, a2, a3, bfr[nt][0], bfr[nt][1]);
            }
        }
        __syncthreads();
    }
    #undef ISSUE_STAGE_F16
}

#define MMA_SMEM_BYTES 65536

// ============================================================
// Stage 0a: transpose x[b,c,n] -> xt[b,n,c]
// ============================================================
__global__ __launch_bounds__(256) void transpose_kernel(const float* __restrict__ x)
{
    __shared__ float tile[32][33];
    const int b  = blockIdx.z;
    const int n0 = blockIdx.x * 32;
    const int c0 = blockIdx.y * 32;
    const int tx = threadIdx.x & 31;
    const int ty = threadIdx.x >> 5;

    const float* X = x + (size_t)b * CH * NPIX;
    float* XT = g_xt + (size_t)b * NPIX * CH;

    #pragma unroll
    for (int r = 0; r < 4; r++) {
        int c = ty + r * 8;
        tile[c][tx] = X[(size_t)(c0 + c) * NPIX + n0 + tx];
    }
    __syncthreads();
    #pragma unroll
    for (int r = 0; r < 4; r++) {
        int n = ty + r * 8;
        XT[(size_t)(n0 + n) * CH + c0 + tx] = tile[tx][n];
    }
}

// ============================================================
// Stage 0b: concat Wq,Wk -> g_wqk [128 rows x 512]
// ============================================================
__global__ __launch_bounds__(256) void concat_w_kernel(
    const float* __restrict__ Wq, const float* __restrict__ Wk)
{
    int i = blockIdx.x * 256 + threadIdx.x;   // 0 .. 128*512-1
    g_wqk[i] = (i < DQK * CH) ? Wq[i] : Wk[i - DQK * CH];
}

// ============================================================
// Stage 1a: Q+K projection, tf32 mma.
// A = [Wq;Wk] (128 x 512), B = xt rows n (128 x 512).
// Epilogue: +bias, scatter transposed into qt/kt [n][d].
// ============================================================
__global__ __launch_bounds__(256, 2) void proj_qk_mma_kernel(
    const float* __restrict__ bq, const float* __restrict__ bk)
{
    const int b  = blockIdx.y;
    const int n0 = blockIdx.x * 128;

    const float* A = g_wqk;
    const float* B = g_xt + ((size_t)b * NPIX + n0) * CH;

    float acc[4][4][4] = {};
    nt_mma_mainloop<CH>(A, CH, B, CH, acc);

    const int tid  = threadIdx.x;
    const int lane = tid & 31;
    const int warp_m = (tid >> 5) >> 2;
    const int warp_n = (tid >> 5) & 3;
    const int gq = lane >> 2;
    const int qc = (lane & 3) * 2;

    float* QT = g_qt + (size_t)b * NPIX * DQK;
    float* KT = g_kt + (size_t)b * NPIX * DQK;

    #pragma unroll
    for (int mt = 0; mt < 4; mt++) {
        #pragma unroll
        for (int h = 0; h < 2; h++) {
            int m = warp_m * 64 + mt * 16 + gq + h * 8;   // 0..127 (0-63=q, 64-127=k)
            int d = m & 63;
            float bias = (m < 64) ? bq[d] : bk[d];
            float* T = (m < 64) ? QT : KT;
            #pragma unroll
            for (int nt = 0; nt < 4; nt++) {
                int n = n0 + warp_n * 32 + nt * 8 + qc;
                T[(size_t)n * DQK + d]       = acc[mt][nt][h * 2 + 0] + bias;
                T[(size_t)(n + 1) * DQK + d] = acc[mt][nt][h * 2 + 1] + bias;
            }
        }
    }
}

// ============================================================
// Stage 1b: V projection, tf32 mma; writes fp16 V.
// ============================================================
__global__ __launch_bounds__(256, 2) void projv_mma_kernel(
    const float* __restrict__ Wv, const float* __restrict__ bv)
{
    const int b  = blockIdx.z;
    const int m0 = blockIdx.y * 128;
    const int n0 = blockIdx.x * 128;

    const float* A = Wv + (size_t)m0 * CH;
    const float* B = g_xt + ((size_t)b * NPIX + n0) * CH;

    float acc[4][4][4] = {};
    nt_mma_mainloop<CH>(A, CH, B, CH, acc);

    const int tid  = threadIdx.x;
    const int lane = tid & 31;
    const int warp_m = (tid >> 5) >> 2;
    const int warp_n = (tid >> 5) & 3;
    const int gq = lane >> 2;
    const int qc = (lane & 3) * 2;

    __half* Vb = g_vh + (size_t)b * CH * NPIX;
    #pragma unroll
    for (int mt = 0; mt < 4; mt++) {
        int m_base = m0 + warp_m * 64 + mt * 16;
        #pragma unroll
        for (int nt = 0; nt < 4; nt++) {
            int n_base = n0 + warp_n * 32 + nt * 8;
            #pragma unroll
            for (int h = 0; h < 2; h++) {
                int m = m_base + gq + h * 8;
                float bias = bv[m];
                __half2 hv = __floats2half2_rn(acc[mt][nt][h * 2 + 0] + bias,
                                               acc[mt][nt][h * 2 + 1] + bias);
                *reinterpret_cast<__half2*>(Vb + (size_t)m * NPIX + n_base + qc) = hv;
            }
        }
    }
}

// ============================================================
// Stage 2: scores, tf32 mma (fp32 output -- precision-critical).
// ============================================================
__global__ __launch_bounds__(256, 2) void scores_mma_kernel()
{
    const int b  = blockIdx.z;
    const int i0 = blockIdx.y * 128;
    const int j0 = blockIdx.x * 128;

    const float* A = g_qt + ((size_t)b * NPIX + i0) * DQK;
    const float* B = g_kt + ((size_t)b * NPIX + j0) * DQK;

    float acc[4][4][4] = {};
    nt_mma_mainloop<DQK>(A, DQK, B, DQK, acc);

    const int tid  = threadIdx.x;
    const int lane = tid & 31;
    const int warp_m = (tid >> 5) >> 2;
    const int warp_n = (tid >> 5) & 3;
    const int gq = lane >> 2;
    const int qc = (lane & 3) * 2;

    float* S = g_p + (size_t)b * NPIX * NPIX;
    #pragma unroll
    for (int mt = 0; mt < 4; mt++) {
        int i_base = i0 + warp_m * 64 + mt * 16;
        #pragma unroll
        for (int nt = 0; nt < 4; nt++) {
            int j_base = j0 + warp_n * 32 + nt * 8;
            #pragma unroll
            for (int h = 0; h < 2; h++) {
                float2 ov;
                ov.x = acc[mt][nt][h * 2 + 0];
                ov.y = acc[mt][nt][h * 2 + 1];
                *reinterpret_cast<float2*>(S + (size_t)(i_base + gq + h * 8) * NPIX + j_base + qc) = ov;
            }
        }
    }
}

// ============================================================
// Stage 3: softmax; reads fp32 S, writes fp16 P.
// ============================================================
__global__ __launch_bounds__(256) void softmax_kernel()
{
    const size_t row = blockIdx.x;
    const float* S = g_p  + row * NPIX;
    __half*      P = g_ph + row * NPIX;
    const int tid = threadIdx.x;

    float4 vals[4];
    float m = -1e30f;
    #pragma unroll
    for (int t = 0; t < 4; t++) {
        vals[t] = reinterpret_cast<const float4*>(S)[tid + t * 256];
        m = fmaxf(m, fmaxf(fmaxf(vals[t].x, vals[t].y), fmaxf(vals[t].z, vals[t].w)));
    }

    __shared__ float red[8];
    #pragma unroll
    for (int o = 16; o; o >>= 1) m = fmaxf(m, __shfl_xor_sync(0xffffffffu, m, o));
    if ((tid & 31) == 0) red[tid >> 5] = m;
    __syncthreads();
    m = red[0];
    #pragma unroll
    for (int w = 1; w < 8; w++) m = fmaxf(m, red[w]);
    __syncthreads();

    float l = 0.f;
    #pragma unroll
    for (int t = 0; t < 4; t++) {
        vals[t].x = __expf(vals[t].x - m);
        vals[t].y = __expf(vals[t].y - m);
        vals[t].z = __expf(vals[t].z - m);
        vals[t].w = __expf(vals[t].w - m);
        l += (vals[t].x + vals[t].y) + (vals[t].z + vals[t].w);
    }
    #pragma unroll
    for (int o = 16; o; o >>= 1) l += __shfl_xor_sync(0xffffffffu, l, o);
    if ((tid & 31) == 0) red[tid >> 5] = l;
    __syncthreads();
    l = 0.f;
    #pragma unroll
    for (int w = 0; w < 8; w++) l += red[w];

    const float inv = 1.0f / l;
    #pragma unroll
    for (int t = 0; t < 4; t++) {
        __half2 h0 = __floats2half2_rn(vals[t].x * inv, vals[t].y * inv);
        __half2 h1 = __floats2half2_rn(vals[t].z * inv, vals[t].w * inv);
        uint2 pk;
        pk.x = *reinterpret_cast<uint32_t*>(&h0);
        pk.y = *reinterpret_cast<uint32_t*>(&h1);
        reinterpret_cast<uint2*>(P)[tid + t * 256] = pk;
    }
}

// ============================================================
// Stage 4: PV, fp16 mma.  out = gamma * (V P^T) + x
// ============================================================
__global__ __launch_bounds__(256, 2) void pv_mma_kernel(
    const float* __restrict__ x, const float* __restrict__ gamma_p,
    float* __restrict__ out)
{
    const int b  = blockIdx.z;
    const int c0 = blockIdx.y * 128;
    const int i0 = blockIdx.x * 128;

    const __half* A = g_vh + (size_t)b * CH * NPIX + (size_t)c0 * NPIX;
    const __half* B = g_ph + (size_t)b * NPIX * NPIX + (size_t)i0 * NPIX;

    float acc[4][4][4] = {};
    nt_mma_mainloop_f16<NPIX>(A, NPIX, B, NPIX, acc);

    const int tid  = threadIdx.x;
    const int lane = tid & 31;
    const int warp_m = (tid >> 5) >> 2;
    const int warp_n = (tid >> 5) & 3;
    const int gq = lane >> 2;
    const int qc = (lane & 3) * 2;

    const float g = *gamma_p;
    const float* Xb = x   + (size_t)b * CH * NPIX;
    float*       Ob = out + (size_t)b * CH * NPIX;

    #pragma unroll
    for (int mt = 0; mt < 4; mt++) {
        int c_base = c0 + warp_m * 64 + mt * 16;
        #pragma unroll
        for (int nt = 0; nt < 4; nt++) {
            int i_base = i0 + warp_n * 32 + nt * 8;
            #pragma unroll
            for (int h = 0; h < 2; h++) {
                size_t idx = (size_t)(c_base + gq + h * 8) * NPIX + i_base + qc;
                float2 xv = *reinterpret_cast<const float2*>(Xb + idx);
                float2 ov;
                ov.x = fmaf(g, acc[mt][nt][h * 2 + 0], xv.x);
                ov.y = fmaf(g, acc[mt][nt][h * 2 + 1], xv.y);
                *reinterpret_cast<float2*>(Ob + idx) = ov;
            }
        }
    }
}

// ============================================================
// launch
// ============================================================
extern "C" void kernel_launch(void* const* d_in, const int* in_sizes, int n_in,
                              void* d_out, int out_size)
{
    const float* x     = (const float*)d_in[0];
    const float* Wq    = (const float*)d_in[1];
    const float* bq    = (const float*)d_in[2];
    const float* Wk    = (const float*)d_in[3];
    const float* bk    = (const float*)d_in[4];
    const float* Wv    = (const float*)d_in[5];
    const float* bv    = (const float*)d_in[6];
    const float* gamma = (const float*)d_in[7];
    float* out = (float*)d_out;

    cudaFuncSetAttribute(proj_qk_mma_kernel, cudaFuncAttributeMaxDynamicSharedMemorySize, MMA_SMEM_BYTES);
    cudaFuncSetAttribute(projv_mma_kernel,   cudaFuncAttributeMaxDynamicSharedMemorySize, MMA_SMEM_BYTES);
    cudaFuncSetAttribute(scores_mma_kernel,  cudaFuncAttributeMaxDynamicSharedMemorySize, MMA_SMEM_BYTES);
    cudaFuncSetAttribute(pv_mma_kernel,      cudaFuncAttributeMaxDynamicSharedMemorySize, MMA_SMEM_BYTES);

    // Stage 0: weight concat (independent) + x transpose
    concat_w_kernel<<<128 * CH / 256, 256>>>(Wq, Wk);
    {
        dim3 grid(NPIX / 32, CH / 32, BATCH);
        transpose_kernel<<<grid, 256>>>(x);
    }
    // Stage 1: projections (both tf32 mma over g_xt)
    {
        dim3 gridqk(NPIX / 128, BATCH);
        proj_qk_mma_kernel<<<gridqk, 256, MMA_SMEM_BYTES>>>(bq, bk);
        dim3 gridv(NPIX / 128, CH / 128, BATCH);
        projv_mma_kernel<<<gridv, 256, MMA_SMEM_BYTES>>>(Wv, bv);
    }
    // Stage 2: scores
    {
        dim3 grid(NPIX / 128, NPIX / 128, BATCH);
        scores_mma_kernel<<<grid, 256, MMA_SMEM_BYTES>>>();
    }
    // Stage 3: softmax (fp32 -> fp16)
    softmax_kernel<<<BATCH * NPIX, 256>>>();
    // Stage 4: PV (fp16) + epilogue
    {
        dim3 grid(NPIX / 128, CH / 128, BATCH);
        pv_mma_kernel<<<grid, 256, MMA_SMEM_BYTES>>>(x, gamma, out);
    }
}